// round 12
// baseline (speedup 1.0000x reference)
#include <cuda_runtime.h>
#include <cuda_bf16.h>
#include <cstdint>

#define BB 16
#define NN 8192
#define HH 128
#define GG 10
#define DCC 16
#define NBLK 6
#define K1 154
#define KPROJ0 272
#define KBLK 282
#define NP 128          // points per local CTA
#define NT 64           // local tiles per batch
#define NPART 128
#define NT0 32

// ---- k_local SMEM (bytes): int8 tiles stride 144 (9x16B, conflict-free) ----
#define SB8 144
#define TI (HH * SB8)           // 18432
#define O_A1H 0
#define O_A1L (TI)
#define O_A2H (2 * TI)
#define O_A2L (3 * TI)
#define O_B1H (4 * TI)
#define O_B1L (5 * TI)
#define O_B2H 0                 // h tile overlays A1 after stage-1
#define O_B2L (TI)
#define O_STG (6 * TI)          // fp32 staging [128][129] = 66048 (last block)
#define O_MS  (O_STG + 66048)   // 176640
#define S_W1  (O_MS)
#define S_W2  (O_MS + 512)
#define S_X1  (O_MS + 1024)
#define S_X2  (O_MS + 1536)
#define O_B1V (O_MS + 2048)
#define O_B2V (O_MS + 2560)
#define O_MK  (O_MS + 3072)
#define O_OW  (O_MS + 3584)
#define O_OB  (O_MS + 5120)
#define O_CMX (O_MS + 5136)     // float [8][128] = 4096 (also prologue cm4[4][128])
#define SMEM_SZ (O_MS + 9232)   // 185872

typedef unsigned int u32;
typedef signed char s8;

// persistent scratch
__device__ float g_xl[(size_t)BB * HH * NN];      // (B, H, N)
__device__ float g_part[BB * NPART * HH];
__device__ float g_part0[BB * NT0 * HH];
__device__ float g_cnt0[BB * NT0];
__device__ float g_cnt[BB];
__device__ float g_xg[BB * GG];
__device__ float g_hb[BB * HH];                   // folded W1[:,128:154]@[xg;ctx]
__device__ s8    g_wh[2 * NBLK * HH * HH];        // pre-quantized weight hi plane
__device__ s8    g_wl[2 * NBLK * HH * HH];        // lo plane
__device__ float g_ws[2 * NBLK * HH];             // per-row weight scales

__device__ __forceinline__ float lrelu(float v) { return fmaxf(v, 0.01f * v); }

__device__ __forceinline__ u32 s2u(const void* p) {
    u32 a;
    asm("{ .reg .u64 t; cvta.to.shared.u64 t, %1; cvt.u32.u64 %0, t; }" : "=r"(a) : "l"(p));
    return a;
}

#define LDM4(r, addr) \
    asm volatile("ldmatrix.sync.aligned.m8n8.x4.shared.b16 {%0,%1,%2,%3}, [%4];" \
        : "=r"((r)[0]), "=r"((r)[1]), "=r"((r)[2]), "=r"((r)[3]) : "r"(addr))

#define MMA_I8(c, a, b0_, b1_) \
    asm volatile("mma.sync.aligned.m16n8k32.row.col.s32.s8.s8.s32 " \
        "{%0,%1,%2,%3}, {%4,%5,%6,%7}, {%8,%9}, {%0,%1,%2,%3};" \
        : "+r"((c)[0]), "+r"((c)[1]), "+r"((c)[2]), "+r"((c)[3]) \
        : "r"((a)[0]), "r"((a)[1]), "r"((a)[2]), "r"((a)[3]), "r"(b0_), "r"(b1_))

__device__ __forceinline__ void qsplit(float v, float inv_s, s8& qh, s8& ql) {
    int q = __float2int_rn(v * inv_s);
    int h = (q + 64) >> 7;
    qh = (s8)h;
    ql = (s8)(q - (h << 7));
}

// D[16 x 64 per warp]: 3-term int8 fixed-point GEMM over K=128 (4 k-steps).
__device__ __forceinline__ void gemm_i8(u32 aH, u32 aL, u32 bH, u32 bL,
                                        int lane, int m_base, int n_base,
                                        int* a14, int* a7)
{
    u32 aOff  = aH + (u32)(m_base + (lane & 15)) * SB8 + ((lane & 16) ? 16u : 0u);
    u32 aOffL = aOff + (aL - aH);
    u32 bR = (u32)((lane & 7) + ((lane & 16) >> 1));
    u32 bOff  = bH + ((u32)n_base + bR) * SB8 + ((lane & 8) ? 16u : 0u);
    u32 bOffL = bOff + (bL - bH);
    #pragma unroll
    for (int ks = 0; ks < 4; ++ks) {
        u32 ak = (u32)ks * 32u;
        u32 ah[4], al[4];
        LDM4(ah, aOff + ak);
        LDM4(al, aOffL + ak);
        u32 bh[4][4];
        #pragma unroll
        for (int bt = 0; bt < 4; ++bt) LDM4(bh[bt], bOff + (u32)(bt * 16) * SB8 + ak);
        #pragma unroll
        for (int bt = 0; bt < 4; ++bt) {
            MMA_I8(a14 + 8 * bt,     ah, bh[bt][0], bh[bt][1]);
            MMA_I8(a14 + 8 * bt + 4, ah, bh[bt][2], bh[bt][3]);
        }
        #pragma unroll
        for (int bt = 0; bt < 4; ++bt) {
            MMA_I8(a7 + 8 * bt,     al, bh[bt][0], bh[bt][1]);
            MMA_I8(a7 + 8 * bt + 4, al, bh[bt][2], bh[bt][3]);
        }
        u32 bl[4][4];
        #pragma unroll
        for (int bt = 0; bt < 4; ++bt) LDM4(bl[bt], bOffL + (u32)(bt * 16) * SB8 + ak);
        #pragma unroll
        for (int bt = 0; bt < 4; ++bt) {
            MMA_I8(a7 + 8 * bt,     ah, bl[bt][0], bl[bt][1]);
            MMA_I8(a7 + 8 * bt + 4, ah, bl[bt][2], bl[bt][3]);
        }
    }
}

// ---------------------------------------------------------------------------
// k_prep: quantize W1[:, :128] and W2 per block, per-row 15-bit scales.
// grid (NBLK, 2), 128 threads (thread = row).
// ---------------------------------------------------------------------------
__global__ __launch_bounds__(128) void k_prep(const float* __restrict__ l1w,
                                              const float* __restrict__ l2w)
{
    int blk = blockIdx.x, mat = blockIdx.y, m = threadIdx.x;
    const float* row = (mat == 0) ? (l1w + ((size_t)blk * HH + m) * K1)
                                  : (l2w + ((size_t)blk * HH + m) * HH);
    float mx = 0.f;
    for (int k = 0; k < HH; ++k) mx = fmaxf(mx, fabsf(row[k]));
    float s = fmaxf(mx, 1e-30f) / 16256.f;
    int base = (mat * NBLK + blk) * HH + m;
    g_ws[base] = s;
    s8* oh = g_wh + (size_t)base * HH;
    s8* ol = g_wl + (size_t)base * HH;
    float inv = 1.f / s;
    for (int k = 0; k < HH; ++k) {
        s8 qh, ql; qsplit(row[k], inv, qh, ql);
        oh[k] = qh; ol[k] = ql;
    }
}

// ---------------------------------------------------------------------------
// k_proj (unchanged from R11)
// ---------------------------------------------------------------------------
__global__ __launch_bounds__(256) void k_proj(
    const float* __restrict__ x, const float* __restrict__ mask,
    const float* __restrict__ lw, const float* __restrict__ lb)
{
    __shared__ float sw[HH * 3], sbv[HH], st[32][257], sp[HH], sc[8];
    int b = blockIdx.x, tile = blockIdx.y, tid = threadIdx.x;
    int wid = tid >> 5, lid = tid & 31;
    int p0 = tile * 256, p = p0 + tid;
    for (int i = tid; i < HH * 3; i += 256) sw[i] = lw[i];
    for (int i = tid; i < HH; i += 256) { sbv[i] = lb[i]; sp[i] = 0.f; }
    __syncthreads();
    const float* xr = x + ((size_t)b * NN + p) * 3;
    float x0 = xr[0], x1 = xr[1], x2 = xr[2];
    float m = mask[(size_t)b * NN + p];
    float cacc = m;
    #pragma unroll
    for (int o = 16; o; o >>= 1) cacc += __shfl_xor_sync(0xffffffffu, cacc, o);
    if (lid == 0) sc[wid] = cacc;

    for (int hc = 0; hc < 4; ++hc) {
        #pragma unroll
        for (int r = 0; r < 32; ++r) {
            int h = hc * 32 + r;
            float v = fmaf(x0, sw[h * 3], fmaf(x1, sw[h * 3 + 1], fmaf(x2, sw[h * 3 + 2], sbv[h])));
            st[r][tid] = lrelu(v) * m;
        }
        __syncthreads();
        for (int idx = tid; idx < 32 * 256; idx += 256) {
            int r = idx >> 8, q = idx & 255;
            g_xl[(size_t)b * HH * NN + (size_t)(hc * 32 + r) * NN + p0 + q] = st[r][q];
        }
        #pragma unroll
        for (int rr = 0; rr < 4; ++rr) {
            int r = wid * 4 + rr;
            float a = 0.f;
            #pragma unroll
            for (int q = 0; q < 8; ++q) a += st[r][lid + q * 32];
            #pragma unroll
            for (int o = 16; o; o >>= 1) a += __shfl_xor_sync(0xffffffffu, a, o);
            if (lid == 0) sp[hc * 32 + r] += a;
        }
        __syncthreads();
    }
    if (tid < HH) g_part0[(b * NT0 + tile) * HH + tid] = sp[tid];
    if (tid == 0) {
        float c = 0.f;
        #pragma unroll
        for (int i = 0; i < 8; ++i) c += sc[i];
        g_cnt0[b * NT0 + tile] = c;
    }
}

// ---------------------------------------------------------------------------
// k_global (unchanged from R11): global MLP + folded bias
// ---------------------------------------------------------------------------
__device__ __forceinline__ float dotw(const float* __restrict__ w,
                                      const float* __restrict__ xs, int n, int lid) {
    float a = 0.f;
    for (int k = lid; k < n; k += 32) a = fmaf(w[k], xs[k], a);
    #pragma unroll
    for (int o = 16; o; o >>= 1) a += __shfl_xor_sync(0xffffffffu, a, o);
    return a;
}

__global__ __launch_bounds__(128) void k_global(
    int phase, int blk, const float* __restrict__ ctx,
    const float* __restrict__ pg0w, const float* __restrict__ pg0b,
    const float* __restrict__ pg1w, const float* __restrict__ pg1b,
    const float* __restrict__ pg2w, const float* __restrict__ pg2b,
    const float* __restrict__ g1w, const float* __restrict__ g1b,
    const float* __restrict__ g2w, const float* __restrict__ g2b,
    const float* __restrict__ l1w)
{
    __shared__ float sp[KBLK], spP[KPROJ0], sh[HH], sh2[HH], sxg[GG], sgc[GG + DCC];
    __shared__ float scn;
    int b = blockIdx.x, j = threadIdx.x, wid = j >> 5, lid = j & 31;

    float s = 0.f;
    if (phase == 0) {
        #pragma unroll 8
        for (int c = 0; c < NT0; ++c) s += g_part0[(b * NT0 + c) * HH + j];
        if (j == 0) {
            float cc = 0.f;
            for (int c = 0; c < NT0; ++c) cc += g_cnt0[b * NT0 + c];
            scn = cc; g_cnt[b] = cc;
        }
    } else {
        #pragma unroll 8
        for (int c = 0; c < NPART; ++c) s += g_part[(b * NPART + c) * HH + j];
        if (j == 0) scn = g_cnt[b];
    }
    __syncthreads();
    float cnt = scn;
    sp[j] = s / cnt; sp[HH + j] = s;
    if (phase == 0) {
        spP[j] = s / cnt; spP[HH + j] = s;
        if (j < DCC) spP[2 * HH + j] = ctx[b * DCC + j];
    }
    if (j < DCC) sp[2 * HH + GG + j] = ctx[b * DCC + j];
    if (j < DCC) sgc[GG + j] = ctx[b * DCC + j];
    __syncthreads();

    if (phase == 0) {
        for (int o = wid; o < HH; o += 4) {
            float a = dotw(pg0w + (size_t)o * KPROJ0, spP, KPROJ0, lid);
            if (lid == 0) sh[o] = lrelu(a + pg0b[o]);
        }
        __syncthreads();
        for (int o = wid; o < HH; o += 4) {
            float a = dotw(pg1w + (size_t)o * HH, sh, HH, lid);
            if (lid == 0) sh2[o] = lrelu(a + pg1b[o]);
        }
        __syncthreads();
        for (int o = wid; o < GG; o += 4) {
            float a = dotw(pg2w + (size_t)o * HH, sh2, HH, lid);
            if (lid == 0) sxg[o] = lrelu(a + pg2b[o]);
        }
        __syncthreads();
    } else {
        if (j < GG) sxg[j] = g_xg[b * GG + j];
        __syncthreads();
    }

    if (j < GG) sp[2 * HH + j] = sxg[j];
    __syncthreads();
    for (int o = wid; o < HH; o += 4) {
        float a = dotw(g1w + ((size_t)blk * HH + o) * KBLK, sp, KBLK, lid);
        if (lid == 0) sh[o] = lrelu(a + g1b[blk * HH + o]);
    }
    __syncthreads();
    for (int o = wid; o < GG; o += 4) {
        float a = dotw(g2w + ((size_t)blk * GG + o) * HH, sh, HH, lid) + g2b[blk * GG + o];
        if (lid == 0) {
            float v = lrelu(a + sxg[o]);
            g_xg[b * GG + o] = v;
            sgc[o] = v;
        }
    }
    __syncthreads();

    for (int o = wid; o < HH; o += 4) {
        const float* wrow = l1w + ((size_t)blk * HH + o) * K1 + HH;
        float a = 0.f;
        if (lid < GG + DCC) a = wrow[lid] * sgc[lid];
        #pragma unroll
        for (int of = 16; of; of >>= 1) a += __shfl_xor_sync(0xffffffffu, a, of);
        if (lid == 0) g_hb[b * HH + o] = a;
    }
}

// ---------------------------------------------------------------------------
// k_local: int8 fixed-point two-layer MLP. grid (64, 16), 512 thr = 16 warps.
// ---------------------------------------------------------------------------
extern __shared__ char smem[];

__global__ void __launch_bounds__(512, 1) k_local(
    int blk, int last,
    const float* __restrict__ l1b, const float* __restrict__ l2b,
    const float* __restrict__ mask,
    const float* __restrict__ outw, const float* __restrict__ outb,
    float* __restrict__ dout)
{
    char* sm = smem;
    u32 sb = s2u(sm);
    int tile = blockIdx.x, b = blockIdx.y, tid = threadIdx.x;
    int wid = tid >> 5, lane = tid & 31;
    int p0 = tile * NP;
    int mw = wid & 7, nh = wid >> 3;
    int m_base = mw * 16, n_base = nh * 64;
    float* cmx = (float*)(sm + O_CMX);

    // ---- prologue: copy pre-quantized weight planes (int4, coalesced) ----
    {
        const int4* s1h = (const int4*)(g_wh + (size_t)(0 * NBLK + blk) * HH * HH);
        const int4* s1l = (const int4*)(g_wl + (size_t)(0 * NBLK + blk) * HH * HH);
        const int4* s2h = (const int4*)(g_wh + (size_t)(1 * NBLK + blk) * HH * HH);
        const int4* s2l = (const int4*)(g_wl + (size_t)(1 * NBLK + blk) * HH * HH);
        for (int idx = tid; idx < 1024; idx += 512) {
            int m = idx >> 3, j = idx & 7;
            u32 o = (u32)m * SB8 + (u32)j * 16u;
            *(int4*)(sm + O_A1H + o) = s1h[idx];
            *(int4*)(sm + O_A1L + o) = s1l[idx];
            *(int4*)(sm + O_A2H + o) = s2h[idx];
            *(int4*)(sm + O_A2L + o) = s2l[idx];
        }
    }
    if (tid < HH) {
        ((float*)(sm + S_W1))[tid] = g_ws[(0 * NBLK + blk) * HH + tid];
        ((float*)(sm + S_W2))[tid] = g_ws[(1 * NBLK + blk) * HH + tid];
        *(float*)(sm + O_B1V + tid * 4) = l1b[blk * HH + tid] + g_hb[b * HH + tid];
        *(float*)(sm + O_B2V + tid * 4) = l2b[blk * HH + tid];
        *(float*)(sm + O_MK + tid * 4) = mask[(size_t)b * NN + p0 + tid];
    }
    if (last) {
        for (int idx = tid; idx < 3 * HH; idx += 512) *(float*)(sm + O_OW + idx * 4) = outw[idx];
        if (tid < 3) *(float*)(sm + O_OB + tid * 4) = outb[tid];
    }

    // ---- xl load: per-column max then quantize (values held in regs) ----
    float xv[32];
    int xc = tid & 127, xk0 = tid >> 7;
    {
        const float* xbase = g_xl + (size_t)b * HH * NN + p0;
        float am = 0.f;
        #pragma unroll
        for (int j = 0; j < 32; ++j) {
            xv[j] = xbase[(size_t)(xk0 + 4 * j) * NN + xc];
            am = fmaxf(am, fabsf(xv[j]));
        }
        cmx[xk0 * 128 + xc] = am;
    }
    __syncthreads();
    {
        float mx = fmaxf(fmaxf(cmx[xc], cmx[128 + xc]), fmaxf(cmx[256 + xc], cmx[384 + xc]));
        float s = fmaxf(mx, 1e-30f) / 16256.f;
        if (tid < 128) ((float*)(sm + S_X1))[tid] =
            fmaxf(fmaxf(cmx[tid], cmx[128 + tid]), fmaxf(cmx[256 + tid], cmx[384 + tid])) / 16256.f
            + ((fmaxf(fmaxf(cmx[tid], cmx[128 + tid]), fmaxf(cmx[256 + tid], cmx[384 + tid])) > 0.f) ? 0.f : 1e-34f);
        float inv = 1.f / s;
        #pragma unroll
        for (int j = 0; j < 32; ++j) {
            s8 qh, ql; qsplit(xv[j], inv, qh, ql);
            int k = xk0 + 4 * j;
            *(s8*)(sm + O_B1H + (u32)xc * SB8 + k) = qh;
            *(s8*)(sm + O_B1L + (u32)xc * SB8 + k) = ql;
        }
    }
    __syncthreads();

    // ---- stage 1 GEMM ----
    int a14[32], a7[32];
    #pragma unroll
    for (int i = 0; i < 32; ++i) { a14[i] = 0; a7[i] = 0; }
    gemm_i8(sb + O_A1H, sb + O_A1L, sb + O_B1H, sb + O_B1L, lane, m_base, n_base, a14, a7);
    __syncthreads();   // all warps done with A1 before B2 overlays it

    // ---- epilogue 1: h = lrelu(scale*comb + b1); per-col max; quantize -> B2 ----
    int r = m_base + (lane >> 2);
    float hv[32];
    {
        float swr  = ((const float*)(sm + S_W1))[r];
        float swr8 = ((const float*)(sm + S_W1))[r + 8];
        float b1r  = *(const float*)(sm + O_B1V + r * 4);
        float b1r8 = *(const float*)(sm + O_B1V + (r + 8) * 4);
        #pragma unroll
        for (int np = 0; np < 8; ++np) {
            int c0 = n_base + np * 8 + 2 * (lane & 3);
            float sx0 = ((const float*)(sm + S_X1))[c0];
            float sx1 = ((const float*)(sm + S_X1))[c0 + 1];
            float f0 = (float)a14[np*4+0] * 16384.f + (float)a7[np*4+0] * 128.f;
            float f1 = (float)a14[np*4+1] * 16384.f + (float)a7[np*4+1] * 128.f;
            float f2 = (float)a14[np*4+2] * 16384.f + (float)a7[np*4+2] * 128.f;
            float f3 = (float)a14[np*4+3] * 16384.f + (float)a7[np*4+3] * 128.f;
            hv[np*4+0] = lrelu(swr  * sx0 * f0 + b1r);
            hv[np*4+1] = lrelu(swr  * sx1 * f1 + b1r);
            hv[np*4+2] = lrelu(swr8 * sx0 * f2 + b1r8);
            hv[np*4+3] = lrelu(swr8 * sx1 * f3 + b1r8);
            float m0 = fmaxf(fabsf(hv[np*4+0]), fabsf(hv[np*4+2]));
            float m1 = fmaxf(fabsf(hv[np*4+1]), fabsf(hv[np*4+3]));
            #pragma unroll
            for (int o = 4; o <= 16; o <<= 1) {
                m0 = fmaxf(m0, __shfl_xor_sync(0xffffffffu, m0, o));
                m1 = fmaxf(m1, __shfl_xor_sync(0xffffffffu, m1, o));
            }
            if (lane < 4) { cmx[mw * 128 + c0] = m0; cmx[mw * 128 + c0 + 1] = m1; }
        }
    }
    __syncthreads();
    if (tid < 128) {
        float mx = 0.f;
        #pragma unroll
        for (int w = 0; w < 8; ++w) mx = fmaxf(mx, cmx[w * 128 + tid]);
        ((float*)(sm + S_X2))[tid] = fmaxf(mx, 1e-30f) / 16256.f;
    }
    __syncthreads();
    #pragma unroll
    for (int np = 0; np < 8; ++np) {
        int c0 = n_base + np * 8 + 2 * (lane & 3);
        float i0 = 1.f / ((const float*)(sm + S_X2))[c0];
        float i1 = 1.f / ((const float*)(sm + S_X2))[c0 + 1];
        s8 qh, ql;
        qsplit(hv[np*4+0], i0, qh, ql);
        *(s8*)(sm + O_B2H + (u32)c0 * SB8 + r) = qh; *(s8*)(sm + O_B2L + (u32)c0 * SB8 + r) = ql;
        qsplit(hv[np*4+1], i1, qh, ql);
        *(s8*)(sm + O_B2H + (u32)(c0+1) * SB8 + r) = qh; *(s8*)(sm + O_B2L + (u32)(c0+1) * SB8 + r) = ql;
        qsplit(hv[np*4+2], i0, qh, ql);
        *(s8*)(sm + O_B2H + (u32)c0 * SB8 + r + 8) = qh; *(s8*)(sm + O_B2L + (u32)c0 * SB8 + r + 8) = ql;
        qsplit(hv[np*4+3], i1, qh, ql);
        *(s8*)(sm + O_B2H + (u32)(c0+1) * SB8 + r + 8) = qh; *(s8*)(sm + O_B2L + (u32)(c0+1) * SB8 + r + 8) = ql;
    }
    __syncthreads();

    // ---- stage 2 GEMM ----
    #pragma unroll
    for (int i = 0; i < 32; ++i) { a14[i] = 0; a7[i] = 0; }
    gemm_i8(sb + O_A2H, sb + O_A2L, sb + O_B2H, sb + O_B2L, lane, m_base, n_base, a14, a7);

    // ---- epilogue 2 ----
    float swr  = ((const float*)(sm + S_W2))[r];
    float swr8 = ((const float*)(sm + S_W2))[r + 8];
    float b2r  = *(const float*)(sm + O_B2V + r * 4);
    float b2r8 = *(const float*)(sm + O_B2V + (r + 8) * 4);
    float sumA = 0.f, sumB = 0.f;

    if (!last) {
        #pragma unroll
        for (int np = 0; np < 8; ++np) {
            int c0 = n_base + np * 8 + 2 * (lane & 3);
            float sx0 = ((const float*)(sm + S_X2))[c0];
            float sx1 = ((const float*)(sm + S_X2))[c0 + 1];
            float mk0 = *(const float*)(sm + O_MK + c0 * 4);
            float mk1 = *(const float*)(sm + O_MK + (c0 + 1) * 4);
            float* gr  = g_xl + ((size_t)(b * HH + r)) * NN + p0 + c0;
            float* gr8 = g_xl + ((size_t)(b * HH + r + 8)) * NN + p0 + c0;
            float2 ra = *(const float2*)gr;
            float2 rb = *(const float2*)gr8;
            float f0 = (float)a14[np*4+0] * 16384.f + (float)a7[np*4+0] * 128.f;
            float f1 = (float)a14[np*4+1] * 16384.f + (float)a7[np*4+1] * 128.f;
            float f2 = (float)a14[np*4+2] * 16384.f + (float)a7[np*4+2] * 128.f;
            float f3 = (float)a14[np*4+3] * 16384.f + (float)a7[np*4+3] * 128.f;
            float v0 = lrelu(swr  * sx0 * f0 + b2r  + ra.x) * mk0;
            float v1 = lrelu(swr  * sx1 * f1 + b2r  + ra.y) * mk1;
            float v2 = lrelu(swr8 * sx0 * f2 + b2r8 + rb.x) * mk0;
            float v3 = lrelu(swr8 * sx1 * f3 + b2r8 + rb.y) * mk1;
            *(float2*)gr  = make_float2(v0, v1);
            *(float2*)gr8 = make_float2(v2, v3);
            sumA += v0 + v1; sumB += v2 + v3;
        }
        #pragma unroll
        for (int o = 1; o <= 2; o <<= 1) {
            sumA += __shfl_xor_sync(0xffffffffu, sumA, o);
            sumB += __shfl_xor_sync(0xffffffffu, sumB, o);
        }
        if ((lane & 3) == 0) {
            int pc = b * NPART + tile * 2 + nh;
            g_part[pc * HH + r] = sumA;
            g_part[pc * HH + r + 8] = sumB;
        }
    } else {
        #pragma unroll
        for (int np = 0; np < 8; ++np) {
            int c0 = n_base + np * 8 + 2 * (lane & 3);
            float sx0 = ((const float*)(sm + S_X2))[c0];
            float sx1 = ((const float*)(sm + S_X2))[c0 + 1];
            float mk0 = *(const float*)(sm + O_MK + c0 * 4);
            float mk1 = *(const float*)(sm + O_MK + (c0 + 1) * 4);
            const float* gr  = g_xl + ((size_t)(b * HH + r)) * NN + p0 + c0;
            const float* gr8 = g_xl + ((size_t)(b * HH + r + 8)) * NN + p0 + c0;
            float2 ra = *(const float2*)gr;
            float2 rb = *(const float2*)gr8;
            float f0 = (float)a14[np*4+0] * 16384.f + (float)a7[np*4+0] * 128.f;
            float f1 = (float)a14[np*4+1] * 16384.f + (float)a7[np*4+1] * 128.f;
            float f2 = (float)a14[np*4+2] * 16384.f + (float)a7[np*4+2] * 128.f;
            float f3 = (float)a14[np*4+3] * 16384.f + (float)a7[np*4+3] * 128.f;
            float v0 = lrelu(swr  * sx0 * f0 + b2r  + ra.x) * mk0;
            float v1 = lrelu(swr  * sx1 * f1 + b2r  + ra.y) * mk1;
            float v2 = lrelu(swr8 * sx0 * f2 + b2r8 + rb.x) * mk0;
            float v3 = lrelu(swr8 * sx1 * f3 + b2r8 + rb.y) * mk1;
            *(float*)(sm + O_STG + ((u32)c0 * 129 + r) * 4)           = v0;
            *(float*)(sm + O_STG + ((u32)(c0 + 1) * 129 + r) * 4)     = v1;
            *(float*)(sm + O_STG + ((u32)c0 * 129 + r + 8) * 4)       = v2;
            *(float*)(sm + O_STG + ((u32)(c0 + 1) * 129 + r + 8) * 4) = v3;
        }
        __syncthreads();
        if (tid < NP) {
            int p = tid;
            float mk = *(const float*)(sm + O_MK + p * 4);
            float s0 = *(const float*)(sm + O_OB + 0);
            float s1 = *(const float*)(sm + O_OB + 4);
            float s2 = *(const float*)(sm + O_OB + 8);
            const float* row = (const float*)(sm + O_STG) + (u32)p * 129;
            for (int m = 0; m < HH; ++m) {
                float v = row[m];
                s0 = fmaf(v, *(const float*)(sm + O_OW + m * 4), s0);
                s1 = fmaf(v, *(const float*)(sm + O_OW + (HH + m) * 4), s1);
                s2 = fmaf(v, *(const float*)(sm + O_OW + (2 * HH + m) * 4), s2);
            }
            float* o = dout + ((size_t)b * NN + p0 + p) * 3;
            o[0] = mk * s0; o[1] = mk * s1; o[2] = mk * s2;
        }
    }
}

// ---------------------------------------------------------------------------
extern "C" void kernel_launch(void* const* d_in, const int* in_sizes, int n_in,
                              void* d_out, int out_size)
{
    const float* x_local = (const float*)d_in[0];
    const float* context = (const float*)d_in[1];
    const float* mask    = (const float*)d_in[2];
    const float* proj_lw = (const float*)d_in[3];
    const float* proj_lb = (const float*)d_in[4];
    const float* pg0w    = (const float*)d_in[5];
    const float* pg0b    = (const float*)d_in[6];
    const float* pg1w    = (const float*)d_in[7];
    const float* pg1b    = (const float*)d_in[8];
    const float* pg2w    = (const float*)d_in[9];
    const float* pg2b    = (const float*)d_in[10];
    const float* g1w     = (const float*)d_in[11];
    const float* g1b     = (const float*)d_in[12];
    const float* g2w     = (const float*)d_in[13];
    const float* g2b     = (const float*)d_in[14];
    const float* l1w     = (const float*)d_in[15];
    const float* l1b     = (const float*)d_in[16];
    const float* l2w     = (const float*)d_in[17];
    const float* l2b     = (const float*)d_in[18];
    const float* outw    = (const float*)d_in[19];
    const float* outb    = (const float*)d_in[20];
    float* out = (float*)d_out;

    cudaFuncSetAttribute(k_local, cudaFuncAttributeMaxDynamicSharedMemorySize, SMEM_SZ);

    k_prep<<<dim3(NBLK, 2), 128>>>(l1w, l2w);
    k_proj<<<dim3(16, NT0), 256>>>(x_local, mask, proj_lw, proj_lb);
    for (int blk = 0; blk < NBLK; ++blk) {
        k_global<<<16, 128>>>(blk == 0 ? 0 : 1, blk, context,
                              pg0w, pg0b, pg1w, pg1b, pg2w, pg2b,
                              g1w, g1b, g2w, g2b, l1w);
        k_local<<<dim3(NT, 16), 512, SMEM_SZ>>>(
            blk, blk == NBLK - 1 ? 1 : 0,
            l1b, l2b, mask, outw, outb, out);
    }
}

// round 13
// speedup vs baseline: 1.5830x; 1.5830x over previous
#include <cuda_runtime.h>
#include <cuda_bf16.h>
#include <cstdint>

#define BB 16
#define NN 8192
#define HH 128
#define GG 10
#define DCC 16
#define NBLK 6
#define K1 154          // H + G + DC (global-path cat width)
#define KPROJ0 272
#define KBLK 282
#define NP 128          // points per local CTA
#define NT 64           // local tiles per batch
#define NPART 128       // pooling partial columns per batch (2 per tile)
#define NT0 32          // proj tiles per batch

// ---- k_local SMEM: six 128x128 bf16 tiles, stride 272B (17x16B, conflict-free)
#define SAB 272
#define TILE_B (HH * SAB)       // 34816
#define O_A1H 0
#define O_A1L (TILE_B)
#define O_B1H (2 * TILE_B)
#define O_B1L (3 * TILE_B)
#define O_A2H (4 * TILE_B)
#define O_A2L (5 * TILE_B)
#define O_B2H 0                 // h split overlays A1 after stage-1 sync
#define O_B2L (TILE_B)
#define O_STG 0                 // fp32 staging [128][129] (last block, after GEMM2)
#define O_MB  (6 * TILE_B)      // 208896
#define O_B1V (O_MB)            // l1b + folded xg/ctx term (fp32[128])
#define O_B2V (O_MB + 512)
#define O_MK  (O_MB + 1024)
#define O_OW  (O_MB + 1536)
#define O_OB  (O_MB + 3072)
#define SMEM_SZ (O_MB + 3104)   // 212000 bytes

typedef unsigned int u32;

// persistent scratch (allocation-free rule: __device__ globals)
__device__ float g_xl[(size_t)BB * HH * NN];      // (B, H, N)
__device__ float g_part[BB * NPART * HH];
__device__ float g_part0[BB * NT0 * HH];
__device__ float g_cnt0[BB * NT0];
__device__ float g_cnt[BB];
__device__ float g_xg[BB * GG];
__device__ float g_hb[BB * HH];                   // folded W1[:,128:154]@[xg;ctx]
// pre-split bf16 weight planes, ALREADY in padded smem layout (272B rows).
// per blk: [A1H, A1L, A2H, A2L] planes of TILE_B bytes each.
__device__ char  g_wsp[(size_t)NBLK * 4 * TILE_B];

__device__ __forceinline__ float lrelu(float v) { return fmaxf(v, 0.01f * v); }

__device__ __forceinline__ u32 s2u(const void* p) {
    u32 a;
    asm("{ .reg .u64 t; cvta.to.shared.u64 t, %1; cvt.u32.u64 %0, t; }" : "=r"(a) : "l"(p));
    return a;
}
__device__ __forceinline__ void bsplit(float v, __nv_bfloat16& h, __nv_bfloat16& l) {
    h = __float2bfloat16(v);
    l = __float2bfloat16(v - __bfloat162float(h));
}

#define LDM4(r, addr) \
    asm volatile("ldmatrix.sync.aligned.m8n8.x4.shared.b16 {%0,%1,%2,%3}, [%4];" \
        : "=r"((r)[0]), "=r"((r)[1]), "=r"((r)[2]), "=r"((r)[3]) : "r"(addr))

#define MMA(c, a, b0_, b1_) \
    asm volatile("mma.sync.aligned.m16n8k16.row.col.f32.bf16.bf16.f32 " \
        "{%0,%1,%2,%3}, {%4,%5,%6,%7}, {%8,%9}, {%0,%1,%2,%3};" \
        : "+f"((c)[0]), "+f"((c)[1]), "+f"((c)[2]), "+f"((c)[3]) \
        : "r"((a)[0]), "r"((a)[1]), "r"((a)[2]), "r"((a)[3]), "r"(b0_), "r"(b1_))

// D[16 x 64 per warp] += (2-term split) A[m,k] x B[n,k]^T over K=128.
// 24 MMAs per k-step round-robin over 8 accumulator quads.
__device__ __forceinline__ void gemm_ss(u32 aH, u32 aL, u32 bH, u32 bL,
                                        int lane, int m_base, int n_base, float* acc)
{
    u32 aOff  = aH + (u32)(m_base + (lane & 15)) * SAB + ((lane & 16) ? 16u : 0u);
    u32 aOffL = aOff + (aL - aH);
    u32 bRow = (u32)((lane & 7) + ((lane & 16) >> 1));
    u32 bOff  = bH + ((u32)n_base + bRow) * SAB + ((lane & 8) ? 16u : 0u);
    u32 bOffL = bOff + (bL - bH);
    #pragma unroll 2
    for (int ks = 0; ks < 8; ++ks) {
        u32 ak = (u32)ks * 32u;
        u32 ah[4], al[4];
        LDM4(ah, aOff + ak);
        LDM4(al, aOffL + ak);
        u32 bh[4][4], bl[4][4];
        #pragma unroll
        for (int np = 0; np < 4; ++np) {
            u32 bk = (u32)(np * 16) * SAB + ak;
            LDM4(bh[np], bOff + bk);
            LDM4(bl[np], bOffL + bk);
        }
        #pragma unroll
        for (int np = 0; np < 4; ++np) {
            MMA(acc + 8 * np,     ah, bh[np][0], bh[np][1]);
            MMA(acc + 8 * np + 4, ah, bh[np][2], bh[np][3]);
        }
        #pragma unroll
        for (int np = 0; np < 4; ++np) {
            MMA(acc + 8 * np,     ah, bl[np][0], bl[np][1]);
            MMA(acc + 8 * np + 4, ah, bl[np][2], bl[np][3]);
        }
        #pragma unroll
        for (int np = 0; np < 4; ++np) {
            MMA(acc + 8 * np,     al, bh[np][0], bh[np][1]);
            MMA(acc + 8 * np + 4, al, bh[np][2], bh[np][3]);
        }
    }
}

// ---------------------------------------------------------------------------
// k_prep: split W1[:, :128] and W2 into bf16 hi/lo planes in the padded
// smem layout. grid (NBLK, 2), 128 threads (thread = output row).
// ---------------------------------------------------------------------------
__global__ __launch_bounds__(128) void k_prep(const float* __restrict__ l1w,
                                              const float* __restrict__ l2w)
{
    int blk = blockIdx.x, mat = blockIdx.y, m = threadIdx.x;
    const float* row = (mat == 0) ? (l1w + ((size_t)blk * HH + m) * K1)
                                  : (l2w + ((size_t)blk * HH + m) * HH);
    char* hp = g_wsp + (size_t)blk * 4 * TILE_B + (size_t)(mat * 2 + 0) * TILE_B + (size_t)m * SAB;
    char* lp = g_wsp + (size_t)blk * 4 * TILE_B + (size_t)(mat * 2 + 1) * TILE_B + (size_t)m * SAB;
    for (int k = 0; k < HH; ++k) {
        __nv_bfloat16 h, l; bsplit(row[k], h, l);
        *(__nv_bfloat16*)(hp + 2 * k) = h;
        *(__nv_bfloat16*)(lp + 2 * k) = l;
    }
}

// ---------------------------------------------------------------------------
// k_proj: xl0 = lrelu(x @ proj_lw^T + b) * mask into g_xl (B,H,N),
//         fused pooling partials + mask counts. grid (16, 32), 256 thr.
// ---------------------------------------------------------------------------
__global__ __launch_bounds__(256) void k_proj(
    const float* __restrict__ x, const float* __restrict__ mask,
    const float* __restrict__ lw, const float* __restrict__ lb)
{
    __shared__ float sw[HH * 3], sbv[HH], st[32][257], sp[HH], sc[8];
    int b = blockIdx.x, tile = blockIdx.y, tid = threadIdx.x;
    int wid = tid >> 5, lid = tid & 31;
    int p0 = tile * 256, p = p0 + tid;
    for (int i = tid; i < HH * 3; i += 256) sw[i] = lw[i];
    for (int i = tid; i < HH; i += 256) { sbv[i] = lb[i]; sp[i] = 0.f; }
    __syncthreads();
    const float* xr = x + ((size_t)b * NN + p) * 3;
    float x0 = xr[0], x1 = xr[1], x2 = xr[2];
    float m = mask[(size_t)b * NN + p];
    float cacc = m;
    #pragma unroll
    for (int o = 16; o; o >>= 1) cacc += __shfl_xor_sync(0xffffffffu, cacc, o);
    if (lid == 0) sc[wid] = cacc;

    for (int hc = 0; hc < 4; ++hc) {
        #pragma unroll
        for (int r = 0; r < 32; ++r) {
            int h = hc * 32 + r;
            float v = fmaf(x0, sw[h * 3], fmaf(x1, sw[h * 3 + 1], fmaf(x2, sw[h * 3 + 2], sbv[h])));
            st[r][tid] = lrelu(v) * m;
        }
        __syncthreads();
        for (int idx = tid; idx < 32 * 256; idx += 256) {
            int r = idx >> 8, q = idx & 255;
            g_xl[(size_t)b * HH * NN + (size_t)(hc * 32 + r) * NN + p0 + q] = st[r][q];
        }
        #pragma unroll
        for (int rr = 0; rr < 4; ++rr) {
            int r = wid * 4 + rr;
            float a = 0.f;
            #pragma unroll
            for (int q = 0; q < 8; ++q) a += st[r][lid + q * 32];
            #pragma unroll
            for (int o = 16; o; o >>= 1) a += __shfl_xor_sync(0xffffffffu, a, o);
            if (lid == 0) sp[hc * 32 + r] += a;
        }
        __syncthreads();
    }
    if (tid < HH) g_part0[(b * NT0 + tile) * HH + tid] = sp[tid];
    if (tid == 0) {
        float c = 0.f;
        #pragma unroll
        for (int i = 0; i < 8; ++i) c += sc[i];
        g_cnt0[b * NT0 + tile] = c;
    }
}

// ---------------------------------------------------------------------------
// k_global: global MLP path + folded-bias vector for k_local. grid 16, 128 thr.
// ---------------------------------------------------------------------------
__device__ __forceinline__ float dotw(const float* __restrict__ w,
                                      const float* __restrict__ xs, int n, int lid) {
    float a = 0.f;
    for (int k = lid; k < n; k += 32) a = fmaf(w[k], xs[k], a);
    #pragma unroll
    for (int o = 16; o; o >>= 1) a += __shfl_xor_sync(0xffffffffu, a, o);
    return a;
}

__global__ __launch_bounds__(128) void k_global(
    int phase, int blk, const float* __restrict__ ctx,
    const float* __restrict__ pg0w, const float* __restrict__ pg0b,
    const float* __restrict__ pg1w, const float* __restrict__ pg1b,
    const float* __restrict__ pg2w, const float* __restrict__ pg2b,
    const float* __restrict__ g1w, const float* __restrict__ g1b,
    const float* __restrict__ g2w, const float* __restrict__ g2b,
    const float* __restrict__ l1w)
{
    __shared__ float sp[KBLK], spP[KPROJ0], sh[HH], sh2[HH], sxg[GG], sgc[GG + DCC];
    __shared__ float scn;
    int b = blockIdx.x, j = threadIdx.x, wid = j >> 5, lid = j & 31;

    float s = 0.f;
    if (phase == 0) {
        #pragma unroll 8
        for (int c = 0; c < NT0; ++c) s += g_part0[(b * NT0 + c) * HH + j];
        if (j == 0) {
            float cc = 0.f;
            for (int c = 0; c < NT0; ++c) cc += g_cnt0[b * NT0 + c];
            scn = cc; g_cnt[b] = cc;
        }
    } else {
        #pragma unroll 8
        for (int c = 0; c < NPART; ++c) s += g_part[(b * NPART + c) * HH + j];
        if (j == 0) scn = g_cnt[b];
    }
    __syncthreads();
    float cnt = scn;
    sp[j] = s / cnt; sp[HH + j] = s;
    if (phase == 0) {
        spP[j] = s / cnt; spP[HH + j] = s;
        if (j < DCC) spP[2 * HH + j] = ctx[b * DCC + j];
    }
    if (j < DCC) sp[2 * HH + GG + j] = ctx[b * DCC + j];
    if (j < DCC) sgc[GG + j] = ctx[b * DCC + j];
    __syncthreads();

    if (phase == 0) {
        for (int o = wid; o < HH; o += 4) {
            float a = dotw(pg0w + (size_t)o * KPROJ0, spP, KPROJ0, lid);
            if (lid == 0) sh[o] = lrelu(a + pg0b[o]);
        }
        __syncthreads();
        for (int o = wid; o < HH; o += 4) {
            float a = dotw(pg1w + (size_t)o * HH, sh, HH, lid);
            if (lid == 0) sh2[o] = lrelu(a + pg1b[o]);
        }
        __syncthreads();
        for (int o = wid; o < GG; o += 4) {
            float a = dotw(pg2w + (size_t)o * HH, sh2, HH, lid);
            if (lid == 0) sxg[o] = lrelu(a + pg2b[o]);
        }
        __syncthreads();
    } else {
        if (j < GG) sxg[j] = g_xg[b * GG + j];
        __syncthreads();
    }

    if (j < GG) sp[2 * HH + j] = sxg[j];
    __syncthreads();
    for (int o = wid; o < HH; o += 4) {
        float a = dotw(g1w + ((size_t)blk * HH + o) * KBLK, sp, KBLK, lid);
        if (lid == 0) sh[o] = lrelu(a + g1b[blk * HH + o]);
    }
    __syncthreads();
    for (int o = wid; o < GG; o += 4) {
        float a = dotw(g2w + ((size_t)blk * GG + o) * HH, sh, HH, lid) + g2b[blk * GG + o];
        if (lid == 0) {
            float v = lrelu(a + sxg[o]);
            g_xg[b * GG + o] = v;
            sgc[o] = v;            // NEW xg for the folded bias
        }
    }
    __syncthreads();

    // folded bias: hb[m] = W1[m, 128:154] @ [xg_new; ctx]
    for (int o = wid; o < HH; o += 4) {
        const float* wrow = l1w + ((size_t)blk * HH + o) * K1 + HH;
        float a = 0.f;
        if (lid < GG + DCC) a = wrow[lid] * sgc[lid];
        #pragma unroll
        for (int of = 16; of; of >>= 1) a += __shfl_xor_sync(0xffffffffu, a, of);
        if (lid == 0) g_hb[b * HH + o] = a;
    }
}

// ---------------------------------------------------------------------------
// k_local: mma.sync bf16-split two-layer MLP, K=128 both stages (xg/ctx folded
// into bias). grid (64 tiles, 16 b), 512 thr = 16 warps (8 M x 2 N-halves).
// Weight planes copied straight from pre-split gmem (no cvt in prologue).
// ---------------------------------------------------------------------------
extern __shared__ char smem[];

__global__ void __launch_bounds__(512, 1) k_local(
    int blk, int last,
    const float* __restrict__ l1b, const float* __restrict__ l2b,
    const float* __restrict__ mask,
    const float* __restrict__ outw, const float* __restrict__ outb,
    float* __restrict__ dout)
{
    char* sm = smem;
    u32 sb = s2u(sm);
    int tile = blockIdx.x, b = blockIdx.y, tid = threadIdx.x;
    int wid = tid >> 5, lane = tid & 31;
    int p0 = tile * NP;
    int mw = wid & 7, nh = wid >> 3;
    int m_base = mw * 16, n_base = nh * 64;

    // ---- prologue: copy pre-split weight planes (pure int4 copies) ----
    {
        const int4* src = (const int4*)(g_wsp + (size_t)blk * 4 * TILE_B);
        int4* d1 = (int4*)(sm + O_A1H);          // planes 0,1 -> A1H, A1L (contiguous)
        const int n16 = 2 * TILE_B / 16;
        for (int idx = tid; idx < n16; idx += 512) d1[idx] = src[idx];
        int4* d2 = (int4*)(sm + O_A2H);          // planes 2,3 -> A2H, A2L (contiguous)
        const int4* src2 = src + n16;
        for (int idx = tid; idx < n16; idx += 512) d2[idx] = src2[idx];
    }
    // xl -> B1 (load fp32, split)
    const float* xbase = g_xl + (size_t)b * HH * NN + p0;
    for (int idx = tid; idx < HH * NP; idx += 512) {
        int k = idx >> 7, n = idx & 127;
        __nv_bfloat16 h, l; bsplit(xbase[(size_t)k * NN + n], h, l);
        u32 o = (u32)n * SAB + (u32)k * 2u;
        *(__nv_bfloat16*)(sm + O_B1H + o) = h;
        *(__nv_bfloat16*)(sm + O_B1L + o) = l;
    }
    if (tid < HH) {
        *(float*)(sm + O_B1V + tid * 4) = l1b[blk * HH + tid] + g_hb[b * HH + tid];
        *(float*)(sm + O_B2V + tid * 4) = l2b[blk * HH + tid];
        *(float*)(sm + O_MK + tid * 4) = mask[(size_t)b * NN + p0 + tid];
    }
    if (last) {
        for (int idx = tid; idx < 3 * HH; idx += 512) *(float*)(sm + O_OW + idx * 4) = outw[idx];
        if (tid < 3) *(float*)(sm + O_OB + tid * 4) = outb[tid];
    }
    __syncthreads();

    // ---- stage 1 GEMM: D1 = W1x @ xl^T ----
    float acc[32];
    #pragma unroll
    for (int i = 0; i < 32; ++i) acc[i] = 0.f;
    gemm_ss(sb + O_A1H, sb + O_A1L, sb + O_B1H, sb + O_B1L, lane, m_base, n_base, acc);
    __syncthreads();   // all warps done reading A1 before B2 overwrites it

    // ---- epilogue 1: h = lrelu(D1 + b1 + hb) -> split into B2 ----
    int r = m_base + (lane >> 2);
    {
        float b1r  = *(const float*)(sm + O_B1V + r * 4);
        float b1r8 = *(const float*)(sm + O_B1V + (r + 8) * 4);
        #pragma unroll
        for (int nt = 0; nt < 8; ++nt) {
            int n0 = n_base + nt * 8 + 2 * (lane & 3);
            float v00 = lrelu(acc[nt * 4 + 0] + b1r);
            float v01 = lrelu(acc[nt * 4 + 1] + b1r);
            float v10 = lrelu(acc[nt * 4 + 2] + b1r8);
            float v11 = lrelu(acc[nt * 4 + 3] + b1r8);
            __nv_bfloat16 h, l;
            u32 o00 = (u32)n0 * SAB + (u32)r * 2u;
            u32 o01 = o00 + SAB;
            bsplit(v00, h, l);
            *(__nv_bfloat16*)(sm + O_B2H + o00) = h; *(__nv_bfloat16*)(sm + O_B2L + o00) = l;
            bsplit(v01, h, l);
            *(__nv_bfloat16*)(sm + O_B2H + o01) = h; *(__nv_bfloat16*)(sm + O_B2L + o01) = l;
            u32 o10 = o00 + 16u, o11 = o01 + 16u;  // row r+8
            bsplit(v10, h, l);
            *(__nv_bfloat16*)(sm + O_B2H + o10) = h; *(__nv_bfloat16*)(sm + O_B2L + o10) = l;
            bsplit(v11, h, l);
            *(__nv_bfloat16*)(sm + O_B2H + o11) = h; *(__nv_bfloat16*)(sm + O_B2L + o11) = l;
        }
    }
    __syncthreads();

    // ---- stage 2 GEMM: D2 = W2 @ h^T ----
    #pragma unroll
    for (int i = 0; i < 32; ++i) acc[i] = 0.f;
    gemm_ss(sb + O_A2H, sb + O_A2L, sb + O_B2H, sb + O_B2L, lane, m_base, n_base, acc);

    // ---- epilogue 2: xl_new = lrelu(D2 + b2 + xl) * mask ----
    float b2r  = *(const float*)(sm + O_B2V + r * 4);
    float b2r8 = *(const float*)(sm + O_B2V + (r + 8) * 4);
    float sumA = 0.f, sumB = 0.f;

    if (!last) {
        #pragma unroll
        for (int nt = 0; nt < 8; ++nt) {
            int n0 = n_base + nt * 8 + 2 * (lane & 3);
            float mk0 = *(const float*)(sm + O_MK + n0 * 4);
            float mk1 = *(const float*)(sm + O_MK + (n0 + 1) * 4);
            float* gr  = g_xl + ((size_t)(b * HH + r)) * NN + p0 + n0;
            float* gr8 = g_xl + ((size_t)(b * HH + r + 8)) * NN + p0 + n0;
            float2 ra = *(const float2*)gr;
            float2 rb = *(const float2*)gr8;
            float v0 = lrelu(acc[nt * 4 + 0] + b2r + ra.x) * mk0;
            float v1 = lrelu(acc[nt * 4 + 1] + b2r + ra.y) * mk1;
            float v2 = lrelu(acc[nt * 4 + 2] + b2r8 + rb.x) * mk0;
            float v3 = lrelu(acc[nt * 4 + 3] + b2r8 + rb.y) * mk1;
            *(float2*)gr  = make_float2(v0, v1);
            *(float2*)gr8 = make_float2(v2, v3);
            sumA += v0 + v1; sumB += v2 + v3;
        }
        #pragma unroll
        for (int o = 1; o <= 2; o <<= 1) {
            sumA += __shfl_xor_sync(0xffffffffu, sumA, o);
            sumB += __shfl_xor_sync(0xffffffffu, sumB, o);
        }
        if ((lane & 3) == 0) {
            int pc = b * NPART + tile * 2 + nh;
            g_part[pc * HH + r] = sumA;
            g_part[pc * HH + r + 8] = sumB;
        }
    } else {
        __syncthreads();   // done reading B2 before staging overwrite
        #pragma unroll
        for (int nt = 0; nt < 8; ++nt) {
            int n0 = n_base + nt * 8 + 2 * (lane & 3);
            float mk0 = *(const float*)(sm + O_MK + n0 * 4);
            float mk1 = *(const float*)(sm + O_MK + (n0 + 1) * 4);
            const float* gr  = g_xl + ((size_t)(b * HH + r)) * NN + p0 + n0;
            const float* gr8 = g_xl + ((size_t)(b * HH + r + 8)) * NN + p0 + n0;
            float2 ra = *(const float2*)gr;
            float2 rb = *(const float2*)gr8;
            float v0 = lrelu(acc[nt * 4 + 0] + b2r + ra.x) * mk0;
            float v1 = lrelu(acc[nt * 4 + 1] + b2r + ra.y) * mk1;
            float v2 = lrelu(acc[nt * 4 + 2] + b2r8 + rb.x) * mk0;
            float v3 = lrelu(acc[nt * 4 + 3] + b2r8 + rb.y) * mk1;
            *(float*)(sm + O_STG + ((u32)n0 * 129 + r) * 4)           = v0;
            *(float*)(sm + O_STG + ((u32)(n0 + 1) * 129 + r) * 4)     = v1;
            *(float*)(sm + O_STG + ((u32)n0 * 129 + r + 8) * 4)       = v2;
            *(float*)(sm + O_STG + ((u32)(n0 + 1) * 129 + r + 8) * 4) = v3;
        }
        __syncthreads();
        if (tid < NP) {
            int p = tid;
            float mk = *(const float*)(sm + O_MK + p * 4);
            float s0 = *(const float*)(sm + O_OB + 0);
            float s1 = *(const float*)(sm + O_OB + 4);
            float s2 = *(const float*)(sm + O_OB + 8);
            const float* row = (const float*)(sm + O_STG) + (u32)p * 129;
            for (int m = 0; m < HH; ++m) {
                float v = row[m];
                s0 = fmaf(v, *(const float*)(sm + O_OW + m * 4), s0);
                s1 = fmaf(v, *(const float*)(sm + O_OW + (HH + m) * 4), s1);
                s2 = fmaf(v, *(const float*)(sm + O_OW + (2 * HH + m) * 4), s2);
            }
            float* o = dout + ((size_t)b * NN + p0 + p) * 3;
            o[0] = mk * s0; o[1] = mk * s1; o[2] = mk * s2;
        }
    }
}

// ---------------------------------------------------------------------------
extern "C" void kernel_launch(void* const* d_in, const int* in_sizes, int n_in,
                              void* d_out, int out_size)
{
    const float* x_local = (const float*)d_in[0];
    const float* context = (const float*)d_in[1];
    const float* mask    = (const float*)d_in[2];
    const float* proj_lw = (const float*)d_in[3];
    const float* proj_lb = (const float*)d_in[4];
    const float* pg0w    = (const float*)d_in[5];
    const float* pg0b    = (const float*)d_in[6];
    const float* pg1w    = (const float*)d_in[7];
    const float* pg1b    = (const float*)d_in[8];
    const float* pg2w    = (const float*)d_in[9];
    const float* pg2b    = (const float*)d_in[10];
    const float* g1w     = (const float*)d_in[11];
    const float* g1b     = (const float*)d_in[12];
    const float* g2w     = (const float*)d_in[13];
    const float* g2b     = (const float*)d_in[14];
    const float* l1w     = (const float*)d_in[15];
    const float* l1b     = (const float*)d_in[16];
    const float* l2w     = (const float*)d_in[17];
    const float* l2b     = (const float*)d_in[18];
    const float* outw    = (const float*)d_in[19];
    const float* outb    = (const float*)d_in[20];
    float* out = (float*)d_out;

    cudaFuncSetAttribute(k_local, cudaFuncAttributeMaxDynamicSharedMemorySize, SMEM_SZ);

    k_prep<<<dim3(NBLK, 2), 128>>>(l1w, l2w);
    k_proj<<<dim3(16, NT0), 256>>>(x_local, mask, proj_lw, proj_lb);
    for (int blk = 0; blk < NBLK; ++blk) {
        k_global<<<16, 128>>>(blk == 0 ? 0 : 1, blk, context,
                              pg0w, pg0b, pg1w, pg1b, pg2w, pg2b,
                              g1w, g1b, g2w, g2b, l1w);
        k_local<<<dim3(NT, 16), 512, SMEM_SZ>>>(
            blk, blk == NBLK - 1 ? 1 : 0,
            l1b, l2b, mask, outw, outb, out);
    }
}

// round 14
// speedup vs baseline: 1.5843x; 1.0008x over previous
#include <cuda_runtime.h>
#include <cuda_bf16.h>
#include <cstdint>

#define BB 16
#define NN 8192
#define HH 128
#define GG 10
#define DCC 16
#define NBLK 6
#define K1 154          // H + G + DC (global-path cat width)
#define KPROJ0 272
#define KBLK 282
#define NP 128          // points per local CTA
#define NT 64           // local tiles per batch
#define NPART 256       // pooling partial columns per batch (4 per tile)
#define NT0 32          // proj tiles per batch

// ---- k_local SMEM: six 128x128 bf16 tiles, stride 272B (17x16B, conflict-free)
#define SAB 272
#define TILE_B (HH * SAB)       // 34816
#define O_A1H 0
#define O_A1L (TILE_B)
#define O_B1H (2 * TILE_B)
#define O_B1L (3 * TILE_B)
#define O_A2H (4 * TILE_B)
#define O_A2L (5 * TILE_B)
#define O_B2H 0                 // h split overlays A1 after stage-1 sync
#define O_B2L (TILE_B)
#define O_STG 0                 // fp32 staging [128][129] (last block, after GEMM2)
#define O_MB  (6 * TILE_B)      // 208896
#define O_B1V (O_MB)            // l1b + folded xg/ctx term (fp32[128])
#define O_B2V (O_MB + 512)
#define O_MK  (O_MB + 1024)
#define O_OW  (O_MB + 1536)
#define O_OB  (O_MB + 3072)
#define SMEM_SZ (O_MB + 3104)   // 212000 bytes

typedef unsigned int u32;

// persistent scratch (allocation-free rule: __device__ globals)
__device__ float g_xl[(size_t)BB * HH * NN];      // (B, H, N)
__device__ float g_part[BB * NPART * HH];
__device__ float g_part0[BB * NT0 * HH];
__device__ float g_cnt0[BB * NT0];
__device__ float g_cnt[BB];
__device__ float g_xg[BB * GG];
__device__ float g_hb[BB * HH];                   // folded W1[:,128:154]@[xg;ctx]
// pre-split bf16 weight planes, ALREADY in padded smem layout (272B rows).
__device__ char  g_wsp[(size_t)NBLK * 4 * TILE_B];

__device__ __forceinline__ float lrelu(float v) { return fmaxf(v, 0.01f * v); }

__device__ __forceinline__ u32 s2u(const void* p) {
    u32 a;
    asm("{ .reg .u64 t; cvta.to.shared.u64 t, %1; cvt.u32.u64 %0, t; }" : "=r"(a) : "l"(p));
    return a;
}
__device__ __forceinline__ void bsplit(float v, __nv_bfloat16& h, __nv_bfloat16& l) {
    h = __float2bfloat16(v);
    l = __float2bfloat16(v - __bfloat162float(h));
}

#define LDM4(r, addr) \
    asm volatile("ldmatrix.sync.aligned.m8n8.x4.shared.b16 {%0,%1,%2,%3}, [%4];" \
        : "=r"((r)[0]), "=r"((r)[1]), "=r"((r)[2]), "=r"((r)[3]) : "r"(addr))

#define MMA(c, a, b0_, b1_) \
    asm volatile("mma.sync.aligned.m16n8k16.row.col.f32.bf16.bf16.f32 " \
        "{%0,%1,%2,%3}, {%4,%5,%6,%7}, {%8,%9}, {%0,%1,%2,%3};" \
        : "+f"((c)[0]), "+f"((c)[1]), "+f"((c)[2]), "+f"((c)[3]) \
        : "r"((a)[0]), "r"((a)[1]), "r"((a)[2]), "r"((a)[3]), "r"(b0_), "r"(b1_))

// D[16 x 32 per warp] += (2-term split) A[m,k] x B[n,k]^T over K=128.
// Per k-step: 6 LDM4, 12 MMAs round-robin over 4 accumulator quads.
__device__ __forceinline__ void gemm_ss(u32 aH, u32 aL, u32 bH, u32 bL,
                                        int lane, int m_base, int n_base, float* acc)
{
    u32 aOff  = aH + (u32)(m_base + (lane & 15)) * SAB + ((lane & 16) ? 16u : 0u);
    u32 aOffL = aOff + (aL - aH);
    u32 bRow = (u32)((lane & 7) + ((lane & 16) >> 1));
    u32 bOff  = bH + ((u32)n_base + bRow) * SAB + ((lane & 8) ? 16u : 0u);
    u32 bOffL = bOff + (bL - bH);
    #pragma unroll 2
    for (int ks = 0; ks < 8; ++ks) {
        u32 ak = (u32)ks * 32u;
        u32 ah[4], al[4];
        LDM4(ah, aOff + ak);
        LDM4(al, aOffL + ak);
        u32 bh[2][4], bl[2][4];
        #pragma unroll
        for (int bt = 0; bt < 2; ++bt) {
            u32 bk = (u32)(bt * 16) * SAB + ak;
            LDM4(bh[bt], bOff + bk);
            LDM4(bl[bt], bOffL + bk);
        }
        #pragma unroll
        for (int bt = 0; bt < 2; ++bt) {
            MMA(acc + 8 * bt,     ah, bh[bt][0], bh[bt][1]);
            MMA(acc + 8 * bt + 4, ah, bh[bt][2], bh[bt][3]);
        }
        #pragma unroll
        for (int bt = 0; bt < 2; ++bt) {
            MMA(acc + 8 * bt,     ah, bl[bt][0], bl[bt][1]);
            MMA(acc + 8 * bt + 4, ah, bl[bt][2], bl[bt][3]);
        }
        #pragma unroll
        for (int bt = 0; bt < 2; ++bt) {
            MMA(acc + 8 * bt,     al, bh[bt][0], bh[bt][1]);
            MMA(acc + 8 * bt + 4, al, bh[bt][2], bh[bt][3]);
        }
    }
}

// ---------------------------------------------------------------------------
// k_prep: split W1[:, :128] and W2 into bf16 hi/lo planes in the padded
// smem layout. grid (NBLK, 2), 128 threads (thread = output row).
// ---------------------------------------------------------------------------
__global__ __launch_bounds__(128) void k_prep(const float* __restrict__ l1w,
                                              const float* __restrict__ l2w)
{
    int blk = blockIdx.x, mat = blockIdx.y, m = threadIdx.x;
    const float* row = (mat == 0) ? (l1w + ((size_t)blk * HH + m) * K1)
                                  : (l2w + ((size_t)blk * HH + m) * HH);
    char* hp = g_wsp + (size_t)blk * 4 * TILE_B + (size_t)(mat * 2 + 0) * TILE_B + (size_t)m * SAB;
    char* lp = g_wsp + (size_t)blk * 4 * TILE_B + (size_t)(mat * 2 + 1) * TILE_B + (size_t)m * SAB;
    for (int k = 0; k < HH; ++k) {
        __nv_bfloat16 h, l; bsplit(row[k], h, l);
        *(__nv_bfloat16*)(hp + 2 * k) = h;
        *(__nv_bfloat16*)(lp + 2 * k) = l;
    }
}

// ---------------------------------------------------------------------------
// k_proj: xl0 = lrelu(x @ proj_lw^T + b) * mask into g_xl (B,H,N),
//         fused pooling partials + mask counts. grid (16, 32), 256 thr.
// ---------------------------------------------------------------------------
__global__ __launch_bounds__(256) void k_proj(
    const float* __restrict__ x, const float* __restrict__ mask,
    const float* __restrict__ lw, const float* __restrict__ lb)
{
    __shared__ float sw[HH * 3], sbv[HH], st[32][257], sp[HH], sc[8];
    int b = blockIdx.x, tile = blockIdx.y, tid = threadIdx.x;
    int wid = tid >> 5, lid = tid & 31;
    int p0 = tile * 256, p = p0 + tid;
    for (int i = tid; i < HH * 3; i += 256) sw[i] = lw[i];
    for (int i = tid; i < HH; i += 256) { sbv[i] = lb[i]; sp[i] = 0.f; }
    __syncthreads();
    const float* xr = x + ((size_t)b * NN + p) * 3;
    float x0 = xr[0], x1 = xr[1], x2 = xr[2];
    float m = mask[(size_t)b * NN + p];
    float cacc = m;
    #pragma unroll
    for (int o = 16; o; o >>= 1) cacc += __shfl_xor_sync(0xffffffffu, cacc, o);
    if (lid == 0) sc[wid] = cacc;

    for (int hc = 0; hc < 4; ++hc) {
        #pragma unroll
        for (int r = 0; r < 32; ++r) {
            int h = hc * 32 + r;
            float v = fmaf(x0, sw[h * 3], fmaf(x1, sw[h * 3 + 1], fmaf(x2, sw[h * 3 + 2], sbv[h])));
            st[r][tid] = lrelu(v) * m;
        }
        __syncthreads();
        for (int idx = tid; idx < 32 * 256; idx += 256) {
            int r = idx >> 8, q = idx & 255;
            g_xl[(size_t)b * HH * NN + (size_t)(hc * 32 + r) * NN + p0 + q] = st[r][q];
        }
        #pragma unroll
        for (int rr = 0; rr < 4; ++rr) {
            int r = wid * 4 + rr;
            float a = 0.f;
            #pragma unroll
            for (int q = 0; q < 8; ++q) a += st[r][lid + q * 32];
            #pragma unroll
            for (int o = 16; o; o >>= 1) a += __shfl_xor_sync(0xffffffffu, a, o);
            if (lid == 0) sp[hc * 32 + r] += a;
        }
        __syncthreads();
    }
    if (tid < HH) g_part0[(b * NT0 + tile) * HH + tid] = sp[tid];
    if (tid == 0) {
        float c = 0.f;
        #pragma unroll
        for (int i = 0; i < 8; ++i) c += sc[i];
        g_cnt0[b * NT0 + tile] = c;
    }
}

// ---------------------------------------------------------------------------
// k_global: global MLP path + folded-bias vector for k_local. grid 16, 128 thr.
// ---------------------------------------------------------------------------
__device__ __forceinline__ float dotw(const float* __restrict__ w,
                                      const float* __restrict__ xs, int n, int lid) {
    float a = 0.f;
    for (int k = lid; k < n; k += 32) a = fmaf(w[k], xs[k], a);
    #pragma unroll
    for (int o = 16; o; o >>= 1) a += __shfl_xor_sync(0xffffffffu, a, o);
    return a;
}

__global__ __launch_bounds__(128) void k_global(
    int phase, int blk, const float* __restrict__ ctx,
    const float* __restrict__ pg0w, const float* __restrict__ pg0b,
    const float* __restrict__ pg1w, const float* __restrict__ pg1b,
    const float* __restrict__ pg2w, const float* __restrict__ pg2b,
    const float* __restrict__ g1w, const float* __restrict__ g1b,
    const float* __restrict__ g2w, const float* __restrict__ g2b,
    const float* __restrict__ l1w)
{
    __shared__ float sp[KBLK], spP[KPROJ0], sh[HH], sh2[HH], sxg[GG], sgc[GG + DCC];
    __shared__ float scn;
    int b = blockIdx.x, j = threadIdx.x, wid = j >> 5, lid = j & 31;

    float s = 0.f;
    if (phase == 0) {
        #pragma unroll 8
        for (int c = 0; c < NT0; ++c) s += g_part0[(b * NT0 + c) * HH + j];
        if (j == 0) {
            float cc = 0.f;
            for (int c = 0; c < NT0; ++c) cc += g_cnt0[b * NT0 + c];
            scn = cc; g_cnt[b] = cc;
        }
    } else {
        #pragma unroll 8
        for (int c = 0; c < NPART; ++c) s += g_part[(b * NPART + c) * HH + j];
        if (j == 0) scn = g_cnt[b];
    }
    __syncthreads();
    float cnt = scn;
    sp[j] = s / cnt; sp[HH + j] = s;
    if (phase == 0) {
        spP[j] = s / cnt; spP[HH + j] = s;
        if (j < DCC) spP[2 * HH + j] = ctx[b * DCC + j];
    }
    if (j < DCC) sp[2 * HH + GG + j] = ctx[b * DCC + j];
    if (j < DCC) sgc[GG + j] = ctx[b * DCC + j];
    __syncthreads();

    if (phase == 0) {
        for (int o = wid; o < HH; o += 4) {
            float a = dotw(pg0w + (size_t)o * KPROJ0, spP, KPROJ0, lid);
            if (lid == 0) sh[o] = lrelu(a + pg0b[o]);
        }
        __syncthreads();
        for (int o = wid; o < HH; o += 4) {
            float a = dotw(pg1w + (size_t)o * HH, sh, HH, lid);
            if (lid == 0) sh2[o] = lrelu(a + pg1b[o]);
        }
        __syncthreads();
        for (int o = wid; o < GG; o += 4) {
            float a = dotw(pg2w + (size_t)o * HH, sh2, HH, lid);
            if (lid == 0) sxg[o] = lrelu(a + pg2b[o]);
        }
        __syncthreads();
    } else {
        if (j < GG) sxg[j] = g_xg[b * GG + j];
        __syncthreads();
    }

    if (j < GG) sp[2 * HH + j] = sxg[j];
    __syncthreads();
    for (int o = wid; o < HH; o += 4) {
        float a = dotw(g1w + ((size_t)blk * HH + o) * KBLK, sp, KBLK, lid);
        if (lid == 0) sh[o] = lrelu(a + g1b[blk * HH + o]);
    }
    __syncthreads();
    for (int o = wid; o < GG; o += 4) {
        float a = dotw(g2w + ((size_t)blk * GG + o) * HH, sh, HH, lid) + g2b[blk * GG + o];
        if (lid == 0) {
            float v = lrelu(a + sxg[o]);
            g_xg[b * GG + o] = v;
            sgc[o] = v;            // NEW xg for the folded bias
        }
    }
    __syncthreads();

    // folded bias: hb[m] = W1[m, 128:154] @ [xg_new; ctx]
    for (int o = wid; o < HH; o += 4) {
        const float* wrow = l1w + ((size_t)blk * HH + o) * K1 + HH;
        float a = 0.f;
        if (lid < GG + DCC) a = wrow[lid] * sgc[lid];
        #pragma unroll
        for (int of = 16; of; of >>= 1) a += __shfl_xor_sync(0xffffffffu, a, of);
        if (lid == 0) g_hb[b * HH + o] = a;
    }
}

// ---------------------------------------------------------------------------
// k_local: mma.sync bf16-split two-layer MLP. grid (64 tiles, 16 b),
// 1024 thr = 32 warps (8 M x 4 N-quarters). Warp tile M=16 x N=32;
// acc = 16 regs -> fits 64-reg/thread ceiling, 8 warps/SMSP for latency hiding.
// ---------------------------------------------------------------------------
extern __shared__ char smem[];

__global__ void __launch_bounds__(1024, 1) k_local(
    int blk, int last,
    const float* __restrict__ l1b, const float* __restrict__ l2b,
    const float* __restrict__ mask,
    const float* __restrict__ outw, const float* __restrict__ outb,
    float* __restrict__ dout)
{
    char* sm = smem;
    u32 sb = s2u(sm);
    int tile = blockIdx.x, b = blockIdx.y, tid = threadIdx.x;
    int wid = tid >> 5, lane = tid & 31;
    int p0 = tile * NP;
    int mw = wid & 7, nh = wid >> 3;
    int m_base = mw * 16, n_base = nh * 32;

    // ---- prologue: copy pre-split weight planes (pure int4 copies) ----
    {
        const int4* src = (const int4*)(g_wsp + (size_t)blk * 4 * TILE_B);
        int4* d1 = (int4*)(sm + O_A1H);          // planes 0,1 -> A1H, A1L
        const int n16 = 2 * TILE_B / 16;
        for (int idx = tid; idx < n16; idx += 1024) d1[idx] = src[idx];
        int4* d2 = (int4*)(sm + O_A2H);          // planes 2,3 -> A2H, A2L
        const int4* src2 = src + n16;
        for (int idx = tid; idx < n16; idx += 1024) d2[idx] = src2[idx];
    }
    // xl -> B1 (load fp32, split)
    const float* xbase = g_xl + (size_t)b * HH * NN + p0;
    for (int idx = tid; idx < HH * NP; idx += 1024) {
        int k = idx >> 7, n = idx & 127;
        __nv_bfloat16 h, l; bsplit(xbase[(size_t)k * NN + n], h, l);
        u32 o = (u32)n * SAB + (u32)k * 2u;
        *(__nv_bfloat16*)(sm + O_B1H + o) = h;
        *(__nv_bfloat16*)(sm + O_B1L + o) = l;
    }
    if (tid < HH) {
        *(float*)(sm + O_B1V + tid * 4) = l1b[blk * HH + tid] + g_hb[b * HH + tid];
        *(float*)(sm + O_B2V + tid * 4) = l2b[blk * HH + tid];
        *(float*)(sm + O_MK + tid * 4) = mask[(size_t)b * NN + p0 + tid];
    }
    if (last) {
        for (int idx = tid; idx < 3 * HH; idx += 1024) *(float*)(sm + O_OW + idx * 4) = outw[idx];
        if (tid < 3) *(float*)(sm + O_OB + tid * 4) = outb[tid];
    }
    __syncthreads();

    // ---- stage 1 GEMM: D1 = W1x @ xl^T ----
    float acc[16];
    #pragma unroll
    for (int i = 0; i < 16; ++i) acc[i] = 0.f;
    gemm_ss(sb + O_A1H, sb + O_A1L, sb + O_B1H, sb + O_B1L, lane, m_base, n_base, acc);
    __syncthreads();   // all warps done reading A1 before B2 overwrites it

    // ---- epilogue 1: h = lrelu(D1 + b1 + hb) -> split into B2 ----
    int r = m_base + (lane >> 2);
    {
        float b1r  = *(const float*)(sm + O_B1V + r * 4);
        float b1r8 = *(const float*)(sm + O_B1V + (r + 8) * 4);
        #pragma unroll
        for (int nt = 0; nt < 4; ++nt) {
            int n0 = n_base + nt * 8 + 2 * (lane & 3);
            float v00 = lrelu(acc[nt * 4 + 0] + b1r);
            float v01 = lrelu(acc[nt * 4 + 1] + b1r);
            float v10 = lrelu(acc[nt * 4 + 2] + b1r8);
            float v11 = lrelu(acc[nt * 4 + 3] + b1r8);
            __nv_bfloat16 h, l;
            u32 o00 = (u32)n0 * SAB + (u32)r * 2u;
            u32 o01 = o00 + SAB;
            bsplit(v00, h, l);
            *(__nv_bfloat16*)(sm + O_B2H + o00) = h; *(__nv_bfloat16*)(sm + O_B2L + o00) = l;
            bsplit(v01, h, l);
            *(__nv_bfloat16*)(sm + O_B2H + o01) = h; *(__nv_bfloat16*)(sm + O_B2L + o01) = l;
            u32 o10 = o00 + 16u, o11 = o01 + 16u;  // row r+8
            bsplit(v10, h, l);
            *(__nv_bfloat16*)(sm + O_B2H + o10) = h; *(__nv_bfloat16*)(sm + O_B2L + o10) = l;
            bsplit(v11, h, l);
            *(__nv_bfloat16*)(sm + O_B2H + o11) = h; *(__nv_bfloat16*)(sm + O_B2L + o11) = l;
        }
    }
    __syncthreads();

    // ---- stage 2 GEMM: D2 = W2 @ h^T ----
    #pragma unroll
    for (int i = 0; i < 16; ++i) acc[i] = 0.f;
    gemm_ss(sb + O_A2H, sb + O_A2L, sb + O_B2H, sb + O_B2L, lane, m_base, n_base, acc);

    // ---- epilogue 2: xl_new = lrelu(D2 + b2 + xl) * mask ----
    float b2r  = *(const float*)(sm + O_B2V + r * 4);
    float b2r8 = *(const float*)(sm + O_B2V + (r + 8) * 4);
    float sumA = 0.f, sumB = 0.f;

    if (!last) {
        #pragma unroll
        for (int nt = 0; nt < 4; ++nt) {
            int n0 = n_base + nt * 8 + 2 * (lane & 3);
            float mk0 = *(const float*)(sm + O_MK + n0 * 4);
            float mk1 = *(const float*)(sm + O_MK + (n0 + 1) * 4);
            float* gr  = g_xl + ((size_t)(b * HH + r)) * NN + p0 + n0;
            float* gr8 = g_xl + ((size_t)(b * HH + r + 8)) * NN + p0 + n0;
            float2 ra = *(const float2*)gr;
            float2 rb = *(const float2*)gr8;
            float v0 = lrelu(acc[nt * 4 + 0] + b2r + ra.x) * mk0;
            float v1 = lrelu(acc[nt * 4 + 1] + b2r + ra.y) * mk1;
            float v2 = lrelu(acc[nt * 4 + 2] + b2r8 + rb.x) * mk0;
            float v3 = lrelu(acc[nt * 4 + 3] + b2r8 + rb.y) * mk1;
            *(float2*)gr  = make_float2(v0, v1);
            *(float2*)gr8 = make_float2(v2, v3);
            sumA += v0 + v1; sumB += v2 + v3;
        }
        #pragma unroll
        for (int o = 1; o <= 2; o <<= 1) {
            sumA += __shfl_xor_sync(0xffffffffu, sumA, o);
            sumB += __shfl_xor_sync(0xffffffffu, sumB, o);
        }
        if ((lane & 3) == 0) {
            int pc = b * NPART + tile * 4 + nh;
            g_part[pc * HH + r] = sumA;
            g_part[pc * HH + r + 8] = sumB;
        }
    } else {
        __syncthreads();   // done reading B2 before staging overwrite
        #pragma unroll
        for (int nt = 0; nt < 4; ++nt) {
            int n0 = n_base + nt * 8 + 2 * (lane & 3);
            float mk0 = *(const float*)(sm + O_MK + n0 * 4);
            float mk1 = *(const float*)(sm + O_MK + (n0 + 1) * 4);
            const float* gr  = g_xl + ((size_t)(b * HH + r)) * NN + p0 + n0;
            const float* gr8 = g_xl + ((size_t)(b * HH + r + 8)) * NN + p0 + n0;
            float2 ra = *(const float2*)gr;
            float2 rb = *(const float2*)gr8;
            float v0 = lrelu(acc[nt * 4 + 0] + b2r + ra.x) * mk0;
            float v1 = lrelu(acc[nt * 4 + 1] + b2r + ra.y) * mk1;
            float v2 = lrelu(acc[nt * 4 + 2] + b2r8 + rb.x) * mk0;
            float v3 = lrelu(acc[nt * 4 + 3] + b2r8 + rb.y) * mk1;
            *(float*)(sm + O_STG + ((u32)n0 * 129 + r) * 4)           = v0;
            *(float*)(sm + O_STG + ((u32)(n0 + 1) * 129 + r) * 4)     = v1;
            *(float*)(sm + O_STG + ((u32)n0 * 129 + r + 8) * 4)       = v2;
            *(float*)(sm + O_STG + ((u32)(n0 + 1) * 129 + r + 8) * 4) = v3;
        }
        __syncthreads();
        if (tid < NP) {
            int p = tid;
            float mk = *(const float*)(sm + O_MK + p * 4);
            float s0 = *(const float*)(sm + O_OB + 0);
            float s1 = *(const float*)(sm + O_OB + 4);
            float s2 = *(const float*)(sm + O_OB + 8);
            const float* row = (const float*)(sm + O_STG) + (u32)p * 129;
            for (int m = 0; m < HH; ++m) {
                float v = row[m];
                s0 = fmaf(v, *(const float*)(sm + O_OW + m * 4), s0);
                s1 = fmaf(v, *(const float*)(sm + O_OW + (HH + m) * 4), s1);
                s2 = fmaf(v, *(const float*)(sm + O_OW + (2 * HH + m) * 4), s2);
            }
            float* o = dout + ((size_t)b * NN + p0 + p) * 3;
            o[0] = mk * s0; o[1] = mk * s1; o[2] = mk * s2;
        }
    }
}

// ---------------------------------------------------------------------------
extern "C" void kernel_launch(void* const* d_in, const int* in_sizes, int n_in,
                              void* d_out, int out_size)
{
    const float* x_local = (const float*)d_in[0];
    const float* context = (const float*)d_in[1];
    const float* mask    = (const float*)d_in[2];
    const float* proj_lw = (const float*)d_in[3];
    const float* proj_lb = (const float*)d_in[4];
    const float* pg0w    = (const float*)d_in[5];
    const float* pg0b    = (const float*)d_in[6];
    const float* pg1w    = (const float*)d_in[7];
    const float* pg1b    = (const float*)d_in[8];
    const float* pg2w    = (const float*)d_in[9];
    const float* pg2b    = (const float*)d_in[10];
    const float* g1w     = (const float*)d_in[11];
    const float* g1b     = (const float*)d_in[12];
    const float* g2w     = (const float*)d_in[13];
    const float* g2b     = (const float*)d_in[14];
    const float* l1w     = (const float*)d_in[15];
    const float* l1b     = (const float*)d_in[16];
    const float* l2w     = (const float*)d_in[17];
    const float* l2b     = (const float*)d_in[18];
    const float* outw    = (const float*)d_in[19];
    const float* outb    = (const float*)d_in[20];
    float* out = (float*)d_out;

    cudaFuncSetAttribute(k_local, cudaFuncAttributeMaxDynamicSharedMemorySize, SMEM_SZ);

    k_prep<<<dim3(NBLK, 2), 128>>>(l1w, l2w);
    k_proj<<<dim3(16, NT0), 256>>>(x_local, mask, proj_lw, proj_lb);
    for (int blk = 0; blk < NBLK; ++blk) {
        k_global<<<16, 128>>>(blk == 0 ? 0 : 1, blk, context,
                              pg0w, pg0b, pg1w, pg1b, pg2w, pg2b,
                              g1w, g1b, g2w, g2b, l1w);
        k_local<<<dim3(NT, 16), 1024, SMEM_SZ>>>(
            blk, blk == NBLK - 1 ? 1 : 0,
            l1b, l2b, mask, outw, outb, out);
    }
}

// round 15
// speedup vs baseline: 1.9456x; 1.2281x over previous
#include <cuda_runtime.h>
#include <cuda_bf16.h>
#include <cstdint>

#define BB 16
#define NN 8192
#define HH 128
#define GG 10
#define DCC 16
#define NBLK 6
#define K1 154          // H + G + DC (global-path cat width)
#define KPROJ0 272
#define KBLK 282
#define NP 128          // points per local CTA
#define NT 64           // local tiles per batch
#define NPART 256       // pooling partial columns per batch (4 per tile)
#define NT0 32          // proj tiles per batch

// ---- k_local SMEM: six 128x128 bf16 tiles, stride 272B (17x16B, conflict-free)
#define SAB 272
#define TILE_B (HH * SAB)       // 34816
#define O_A1H 0
#define O_A1L (TILE_B)
#define O_B1H (2 * TILE_B)
#define O_B1L (3 * TILE_B)
#define O_A2H (4 * TILE_B)
#define O_A2L (5 * TILE_B)
#define O_B2H 0                 // h split overlays A1 after stage-1 sync
#define O_B2L (TILE_B)
#define O_STG 0                 // fp32 staging [128][129] (last block, after GEMM2)
#define O_MB  (6 * TILE_B)      // 208896
#define O_B1V (O_MB)            // l1b + folded xg/ctx term (fp32[128])
#define O_B2V (O_MB + 512)
#define O_MK  (O_MB + 1024)
#define O_OW  (O_MB + 1536)
#define O_OB  (O_MB + 3072)
#define SMEM_SZ (O_MB + 3104)   // 212000 bytes

typedef unsigned int u32;

// persistent scratch (allocation-free rule: __device__ globals)
__device__ float g_xl[(size_t)BB * HH * NN];      // (B, H, N)
__device__ float g_part[BB * NPART * HH];
__device__ float g_part0[BB * NT0 * HH];
__device__ float g_cnt0[BB * NT0];
__device__ float g_cnt[BB];
__device__ float g_xg[BB * GG];
__device__ float g_hb[BB * HH];                   // folded W1[:,128:154]@[xg;ctx]
// pre-split bf16 weight planes, ALREADY in padded smem layout (272B rows).
__device__ char  g_wsp[(size_t)NBLK * 4 * TILE_B];

__device__ __forceinline__ float lrelu(float v) { return fmaxf(v, 0.01f * v); }

__device__ __forceinline__ u32 s2u(const void* p) {
    u32 a;
    asm("{ .reg .u64 t; cvta.to.shared.u64 t, %1; cvt.u32.u64 %0, t; }" : "=r"(a) : "l"(p));
    return a;
}
__device__ __forceinline__ void bsplit(float v, __nv_bfloat16& h, __nv_bfloat16& l) {
    h = __float2bfloat16(v);
    l = __float2bfloat16(v - __bfloat162float(h));
}

#define LDM4(r, addr) \
    asm volatile("ldmatrix.sync.aligned.m8n8.x4.shared.b16 {%0,%1,%2,%3}, [%4];" \
        : "=r"((r)[0]), "=r"((r)[1]), "=r"((r)[2]), "=r"((r)[3]) : "r"(addr))

#define MMA(c, a, b0_, b1_) \
    asm volatile("mma.sync.aligned.m16n8k16.row.col.f32.bf16.bf16.f32 " \
        "{%0,%1,%2,%3}, {%4,%5,%6,%7}, {%8,%9}, {%0,%1,%2,%3};" \
        : "+f"((c)[0]), "+f"((c)[1]), "+f"((c)[2]), "+f"((c)[3]) \
        : "r"((a)[0]), "r"((a)[1]), "r"((a)[2]), "r"((a)[3]), "r"(b0_), "r"(b1_))

// D[32 x 32 per warp] += (2-term split) A[m,k] x B[n,k]^T over K=128.
// Per k-step: 8 LDM4 -> 24 MMAs over 8 accumulator quads (reuse distance 8).
__device__ __forceinline__ void gemm32(u32 aH, u32 aL, u32 bH, u32 bL,
                                       int lane, int m_base, int n_base, float* acc)
{
    u32 a0 = aH + (u32)(m_base + (lane & 15)) * SAB + ((lane & 16) ? 16u : 0u);
    u32 dA = aL - aH;
    u32 bRow = (u32)((lane & 7) + ((lane & 16) >> 1));
    u32 b0 = bH + ((u32)n_base + bRow) * SAB + ((lane & 8) ? 16u : 0u);
    u32 dB = bL - bH;
    #pragma unroll 2
    for (int ks = 0; ks < 8; ++ks) {
        u32 ak = (u32)ks * 32u;
        u32 ah[2][4], al[2][4], bh[2][4], bl[2][4];
        LDM4(ah[0], a0 + ak);
        LDM4(ah[1], a0 + 16u * SAB + ak);
        LDM4(bh[0], b0 + ak);
        LDM4(bh[1], b0 + 16u * SAB + ak);
        LDM4(al[0], a0 + dA + ak);
        LDM4(al[1], a0 + dA + 16u * SAB + ak);
        LDM4(bl[0], b0 + dB + ak);
        LDM4(bl[1], b0 + dB + 16u * SAB + ak);
        #pragma unroll
        for (int mi = 0; mi < 2; ++mi)
            #pragma unroll
            for (int nq = 0; nq < 4; ++nq)
                MMA(acc + (mi * 4 + nq) * 4, ah[mi],
                    bh[nq >> 1][(nq & 1) * 2], bh[nq >> 1][(nq & 1) * 2 + 1]);
        #pragma unroll
        for (int mi = 0; mi < 2; ++mi)
            #pragma unroll
            for (int nq = 0; nq < 4; ++nq)
                MMA(acc + (mi * 4 + nq) * 4, ah[mi],
                    bl[nq >> 1][(nq & 1) * 2], bl[nq >> 1][(nq & 1) * 2 + 1]);
        #pragma unroll
        for (int mi = 0; mi < 2; ++mi)
            #pragma unroll
            for (int nq = 0; nq < 4; ++nq)
                MMA(acc + (mi * 4 + nq) * 4, al[mi],
                    bh[nq >> 1][(nq & 1) * 2], bh[nq >> 1][(nq & 1) * 2 + 1]);
    }
}

// ---------------------------------------------------------------------------
// k_prep: split W1[:, :128] and W2 into bf16 hi/lo planes in the padded
// smem layout. grid (NBLK, 2), 128 threads (thread = output row).
// ---------------------------------------------------------------------------
__global__ __launch_bounds__(128) void k_prep(const float* __restrict__ l1w,
                                              const float* __restrict__ l2w)
{
    int blk = blockIdx.x, mat = blockIdx.y, m = threadIdx.x;
    const float* row = (mat == 0) ? (l1w + ((size_t)blk * HH + m) * K1)
                                  : (l2w + ((size_t)blk * HH + m) * HH);
    char* hp = g_wsp + (size_t)blk * 4 * TILE_B + (size_t)(mat * 2 + 0) * TILE_B + (size_t)m * SAB;
    char* lp = g_wsp + (size_t)blk * 4 * TILE_B + (size_t)(mat * 2 + 1) * TILE_B + (size_t)m * SAB;
    for (int k = 0; k < HH; ++k) {
        __nv_bfloat16 h, l; bsplit(row[k], h, l);
        *(__nv_bfloat16*)(hp + 2 * k) = h;
        *(__nv_bfloat16*)(lp + 2 * k) = l;
    }
}

// ---------------------------------------------------------------------------
// k_proj: unchanged.
// ---------------------------------------------------------------------------
__global__ __launch_bounds__(256) void k_proj(
    const float* __restrict__ x, const float* __restrict__ mask,
    const float* __restrict__ lw, const float* __restrict__ lb)
{
    __shared__ float sw[HH * 3], sbv[HH], st[32][257], sp[HH], sc[8];
    int b = blockIdx.x, tile = blockIdx.y, tid = threadIdx.x;
    int wid = tid >> 5, lid = tid & 31;
    int p0 = tile * 256, p = p0 + tid;
    for (int i = tid; i < HH * 3; i += 256) sw[i] = lw[i];
    for (int i = tid; i < HH; i += 256) { sbv[i] = lb[i]; sp[i] = 0.f; }
    __syncthreads();
    const float* xr = x + ((size_t)b * NN + p) * 3;
    float x0 = xr[0], x1 = xr[1], x2 = xr[2];
    float m = mask[(size_t)b * NN + p];
    float cacc = m;
    #pragma unroll
    for (int o = 16; o; o >>= 1) cacc += __shfl_xor_sync(0xffffffffu, cacc, o);
    if (lid == 0) sc[wid] = cacc;

    for (int hc = 0; hc < 4; ++hc) {
        #pragma unroll
        for (int r = 0; r < 32; ++r) {
            int h = hc * 32 + r;
            float v = fmaf(x0, sw[h * 3], fmaf(x1, sw[h * 3 + 1], fmaf(x2, sw[h * 3 + 2], sbv[h])));
            st[r][tid] = lrelu(v) * m;
        }
        __syncthreads();
        for (int idx = tid; idx < 32 * 256; idx += 256) {
            int r = idx >> 8, q = idx & 255;
            g_xl[(size_t)b * HH * NN + (size_t)(hc * 32 + r) * NN + p0 + q] = st[r][q];
        }
        #pragma unroll
        for (int rr = 0; rr < 4; ++rr) {
            int r = wid * 4 + rr;
            float a = 0.f;
            #pragma unroll
            for (int q = 0; q < 8; ++q) a += st[r][lid + q * 32];
            #pragma unroll
            for (int o = 16; o; o >>= 1) a += __shfl_xor_sync(0xffffffffu, a, o);
            if (lid == 0) sp[hc * 32 + r] += a;
        }
        __syncthreads();
    }
    if (tid < HH) g_part0[(b * NT0 + tile) * HH + tid] = sp[tid];
    if (tid == 0) {
        float c = 0.f;
        #pragma unroll
        for (int i = 0; i < 8; ++i) c += sc[i];
        g_cnt0[b * NT0 + tile] = c;
    }
}

// ---------------------------------------------------------------------------
// k_global: 1024 threads / 32 warps. Parallel partial reduce (8 groups x 128)
// + 4 sequential dots per warp instead of 32. grid 16.
// ---------------------------------------------------------------------------
__device__ __forceinline__ float dotw(const float* __restrict__ w,
                                      const float* __restrict__ xs, int n, int lid) {
    float a = 0.f;
    for (int k = lid; k < n; k += 32) a = fmaf(w[k], xs[k], a);
    #pragma unroll
    for (int o = 16; o; o >>= 1) a += __shfl_xor_sync(0xffffffffu, a, o);
    return a;
}

__global__ __launch_bounds__(1024) void k_global(
    int phase, int blk, const float* __restrict__ ctx,
    const float* __restrict__ pg0w, const float* __restrict__ pg0b,
    const float* __restrict__ pg1w, const float* __restrict__ pg1b,
    const float* __restrict__ pg2w, const float* __restrict__ pg2b,
    const float* __restrict__ g1w, const float* __restrict__ g1b,
    const float* __restrict__ g2w, const float* __restrict__ g2b,
    const float* __restrict__ l1w)
{
    __shared__ float red[8][HH];
    __shared__ float sp[KBLK], spP[KPROJ0], sh[HH], sh2[HH], sxg[GG], sgc[GG + DCC];
    __shared__ float scn;
    int b = blockIdx.x, tid = threadIdx.x, wid = tid >> 5, lid = tid & 31;
    int j = tid & 127, grp = tid >> 7;   // 8 groups of 128

    float s = 0.f;
    if (phase == 0) {
        #pragma unroll
        for (int c = grp; c < NT0; c += 8) s += g_part0[(b * NT0 + c) * HH + j];
    } else {
        #pragma unroll 8
        for (int c = grp; c < NPART; c += 8) s += g_part[(b * NPART + c) * HH + j];
    }
    red[grp][j] = s;
    if (wid == 0) {
        float cc;
        if (phase == 0) {
            cc = g_cnt0[b * NT0 + lid];
            #pragma unroll
            for (int o = 16; o; o >>= 1) cc += __shfl_xor_sync(0xffffffffu, cc, o);
            if (lid == 0) { scn = cc; g_cnt[b] = cc; }
        } else if (lid == 0) scn = g_cnt[b];
    }
    __syncthreads();
    float cnt = scn;
    if (tid < HH) {
        float t = 0.f;
        #pragma unroll
        for (int g = 0; g < 8; ++g) t += red[g][tid];
        sp[tid] = t / cnt; sp[HH + tid] = t;
        if (phase == 0) { spP[tid] = t / cnt; spP[HH + tid] = t; }
    }
    if (tid < DCC) {
        float cv = ctx[b * DCC + tid];
        sp[2 * HH + GG + tid] = cv;
        sgc[GG + tid] = cv;
        if (phase == 0) spP[2 * HH + tid] = cv;
    }
    __syncthreads();

    if (phase == 0) {
        for (int o = wid; o < HH; o += 32) {
            float a = dotw(pg0w + (size_t)o * KPROJ0, spP, KPROJ0, lid);
            if (lid == 0) sh[o] = lrelu(a + pg0b[o]);
        }
        __syncthreads();
        for (int o = wid; o < HH; o += 32) {
            float a = dotw(pg1w + (size_t)o * HH, sh, HH, lid);
            if (lid == 0) sh2[o] = lrelu(a + pg1b[o]);
        }
        __syncthreads();
        if (wid < GG) {
            int o = wid;
            float a = dotw(pg2w + (size_t)o * HH, sh2, HH, lid);
            if (lid == 0) sxg[o] = lrelu(a + pg2b[o]);
        }
        __syncthreads();
    } else {
        if (tid < GG) sxg[tid] = g_xg[b * GG + tid];
        __syncthreads();
    }

    if (tid < GG) sp[2 * HH + tid] = sxg[tid];
    __syncthreads();
    for (int o = wid; o < HH; o += 32) {
        float a = dotw(g1w + ((size_t)blk * HH + o) * KBLK, sp, KBLK, lid);
        if (lid == 0) sh[o] = lrelu(a + g1b[blk * HH + o]);
    }
    __syncthreads();
    if (wid < GG) {
        int o = wid;
        float a = dotw(g2w + ((size_t)blk * GG + o) * HH, sh, HH, lid) + g2b[blk * GG + o];
        if (lid == 0) {
            float v = lrelu(a + sxg[o]);
            g_xg[b * GG + o] = v;
            sgc[o] = v;            // NEW xg for the folded bias
        }
    }
    __syncthreads();

    // folded bias: hb[m] = W1[m, 128:154] @ [xg_new; ctx]
    for (int o = wid; o < HH; o += 32) {
        const float* wrow = l1w + ((size_t)blk * HH + o) * K1 + HH;
        float a = 0.f;
        if (lid < GG + DCC) a = wrow[lid] * sgc[lid];
        #pragma unroll
        for (int of = 16; of; of >>= 1) a += __shfl_xor_sync(0xffffffffu, a, of);
        if (lid == 0) g_hb[b * HH + o] = a;
    }
}

// ---------------------------------------------------------------------------
// k_local: mma.sync bf16-split two-layer MLP. grid (64 tiles, 16 b),
// 512 thr = 16 warps (4 M x 4 N), warp tile M32 x N32 (min LDSM traffic).
// ---------------------------------------------------------------------------
extern __shared__ char smem[];

__global__ void __launch_bounds__(512, 1) k_local(
    int blk, int last,
    const float* __restrict__ l1b, const float* __restrict__ l2b,
    const float* __restrict__ mask,
    const float* __restrict__ outw, const float* __restrict__ outb,
    float* __restrict__ dout)
{
    char* sm = smem;
    u32 sb = s2u(sm);
    int tile = blockIdx.x, b = blockIdx.y, tid = threadIdx.x;
    int wid = tid >> 5, lane = tid & 31;
    int p0 = tile * NP;
    int mw = wid & 3, nh = wid >> 2;
    int m_base = mw * 32, n_base = nh * 32;

    // ---- prologue: copy pre-split weight planes (pure int4 copies) ----
    {
        const int4* src = (const int4*)(g_wsp + (size_t)blk * 4 * TILE_B);
        int4* d1 = (int4*)(sm + O_A1H);          // planes 0,1 -> A1H, A1L
        const int n16 = 2 * TILE_B / 16;
        for (int idx = tid; idx < n16; idx += 512) d1[idx] = src[idx];
        int4* d2 = (int4*)(sm + O_A2H);          // planes 2,3 -> A2H, A2L
        const int4* src2 = src + n16;
        for (int idx = tid; idx < n16; idx += 512) d2[idx] = src2[idx];
    }
    // xl -> B1 (load fp32, split)
    const float* xbase = g_xl + (size_t)b * HH * NN + p0;
    for (int idx = tid; idx < HH * NP; idx += 512) {
        int k = idx >> 7, n = idx & 127;
        __nv_bfloat16 h, l; bsplit(xbase[(size_t)k * NN + n], h, l);
        u32 o = (u32)n * SAB + (u32)k * 2u;
        *(__nv_bfloat16*)(sm + O_B1H + o) = h;
        *(__nv_bfloat16*)(sm + O_B1L + o) = l;
    }
    if (tid < HH) {
        *(float*)(sm + O_B1V + tid * 4) = l1b[blk * HH + tid] + g_hb[b * HH + tid];
        *(float*)(sm + O_B2V + tid * 4) = l2b[blk * HH + tid];
        *(float*)(sm + O_MK + tid * 4) = mask[(size_t)b * NN + p0 + tid];
    }
    if (last) {
        for (int idx = tid; idx < 3 * HH; idx += 512) *(float*)(sm + O_OW + idx * 4) = outw[idx];
        if (tid < 3) *(float*)(sm + O_OB + tid * 4) = outb[tid];
    }
    __syncthreads();

    // ---- stage 1 GEMM: D1 = W1x @ xl^T ----
    float acc[32];
    #pragma unroll
    for (int i = 0; i < 32; ++i) acc[i] = 0.f;
    gemm32(sb + O_A1H, sb + O_A1L, sb + O_B1H, sb + O_B1L, lane, m_base, n_base, acc);
    __syncthreads();   // all warps done reading A1 before B2 overwrites it

    // ---- epilogue 1: h = lrelu(D1 + b1 + hb) -> split into B2 ----
    int r0 = lane >> 2;
    #pragma unroll
    for (int mi = 0; mi < 2; ++mi) {
        int rr = m_base + mi * 16 + r0;
        float b1r  = *(const float*)(sm + O_B1V + rr * 4);
        float b1r8 = *(const float*)(sm + O_B1V + (rr + 8) * 4);
        #pragma unroll
        for (int nq = 0; nq < 4; ++nq) {
            int ix = (mi * 4 + nq) * 4;
            int n0 = n_base + nq * 8 + 2 * (lane & 3);
            float v00 = lrelu(acc[ix + 0] + b1r);
            float v01 = lrelu(acc[ix + 1] + b1r);
            float v10 = lrelu(acc[ix + 2] + b1r8);
            float v11 = lrelu(acc[ix + 3] + b1r8);
            __nv_bfloat16 h, l;
            u32 o00 = (u32)n0 * SAB + (u32)rr * 2u;
            u32 o01 = o00 + SAB;
            bsplit(v00, h, l);
            *(__nv_bfloat16*)(sm + O_B2H + o00) = h; *(__nv_bfloat16*)(sm + O_B2L + o00) = l;
            bsplit(v01, h, l);
            *(__nv_bfloat16*)(sm + O_B2H + o01) = h; *(__nv_bfloat16*)(sm + O_B2L + o01) = l;
            u32 o10 = o00 + 16u, o11 = o01 + 16u;  // row rr+8
            bsplit(v10, h, l);
            *(__nv_bfloat16*)(sm + O_B2H + o10) = h; *(__nv_bfloat16*)(sm + O_B2L + o10) = l;
            bsplit(v11, h, l);
            *(__nv_bfloat16*)(sm + O_B2H + o11) = h; *(__nv_bfloat16*)(sm + O_B2L + o11) = l;
        }
    }
    __syncthreads();

    // ---- stage 2 GEMM: D2 = W2 @ h^T ----
    #pragma unroll
    for (int i = 0; i < 32; ++i) acc[i] = 0.f;
    gemm32(sb + O_A2H, sb + O_A2L, sb + O_B2H, sb + O_B2L, lane, m_base, n_base, acc);

    // ---- epilogue 2: xl_new = lrelu(D2 + b2 + xl) * mask ----
    if (!last) {
        #pragma unroll
        for (int mi = 0; mi < 2; ++mi) {
            int rr = m_base + mi * 16 + r0;
            float b2r  = *(const float*)(sm + O_B2V + rr * 4);
            float b2r8 = *(const float*)(sm + O_B2V + (rr + 8) * 4);
            float sumA = 0.f, sumB = 0.f;
            #pragma unroll
            for (int nq = 0; nq < 4; ++nq) {
                int ix = (mi * 4 + nq) * 4;
                int n0 = n_base + nq * 8 + 2 * (lane & 3);
                float mk0 = *(const float*)(sm + O_MK + n0 * 4);
                float mk1 = *(const float*)(sm + O_MK + (n0 + 1) * 4);
                float* gr  = g_xl + ((size_t)(b * HH + rr)) * NN + p0 + n0;
                float* gr8 = g_xl + ((size_t)(b * HH + rr + 8)) * NN + p0 + n0;
                float2 ra = *(const float2*)gr;
                float2 rb = *(const float2*)gr8;
                float v0 = lrelu(acc[ix + 0] + b2r + ra.x) * mk0;
                float v1 = lrelu(acc[ix + 1] + b2r + ra.y) * mk1;
                float v2 = lrelu(acc[ix + 2] + b2r8 + rb.x) * mk0;
                float v3 = lrelu(acc[ix + 3] + b2r8 + rb.y) * mk1;
                *(float2*)gr  = make_float2(v0, v1);
                *(float2*)gr8 = make_float2(v2, v3);
                sumA += v0 + v1; sumB += v2 + v3;
            }
            #pragma unroll
            for (int o = 1; o <= 2; o <<= 1) {
                sumA += __shfl_xor_sync(0xffffffffu, sumA, o);
                sumB += __shfl_xor_sync(0xffffffffu, sumB, o);
            }
            if ((lane & 3) == 0) {
                int pc = b * NPART + tile * 4 + nh;
                g_part[pc * HH + rr] = sumA;
                g_part[pc * HH + rr + 8] = sumB;
            }
        }
    } else {
        __syncthreads();   // done reading B2 before staging overwrite
        #pragma unroll
        for (int mi = 0; mi < 2; ++mi) {
            int rr = m_base + mi * 16 + r0;
            float b2r  = *(const float*)(sm + O_B2V + rr * 4);
            float b2r8 = *(const float*)(sm + O_B2V + (rr + 8) * 4);
            #pragma unroll
            for (int nq = 0; nq < 4; ++nq) {
                int ix = (mi * 4 + nq) * 4;
                int n0 = n_base + nq * 8 + 2 * (lane & 3);
                float mk0 = *(const float*)(sm + O_MK + n0 * 4);
                float mk1 = *(const float*)(sm + O_MK + (n0 + 1) * 4);
                const float* gr  = g_xl + ((size_t)(b * HH + rr)) * NN + p0 + n0;
                const float* gr8 = g_xl + ((size_t)(b * HH + rr + 8)) * NN + p0 + n0;
                float2 ra = *(const float2*)gr;
                float2 rb = *(const float2*)gr8;
                float v0 = lrelu(acc[ix + 0] + b2r + ra.x) * mk0;
                float v1 = lrelu(acc[ix + 1] + b2r + ra.y) * mk1;
                float v2 = lrelu(acc[ix + 2] + b2r8 + rb.x) * mk0;
                float v3 = lrelu(acc[ix + 3] + b2r8 + rb.y) * mk1;
                *(float*)(sm + O_STG + ((u32)n0 * 129 + rr) * 4)           = v0;
                *(float*)(sm + O_STG + ((u32)(n0 + 1) * 129 + rr) * 4)     = v1;
                *(float*)(sm + O_STG + ((u32)n0 * 129 + rr + 8) * 4)       = v2;
                *(float*)(sm + O_STG + ((u32)(n0 + 1) * 129 + rr + 8) * 4) = v3;
            }
        }
        __syncthreads();
        if (tid < NP) {
            int p = tid;
            float mk = *(const float*)(sm + O_MK + p * 4);
            float s0 = *(const float*)(sm + O_OB + 0);
            float s1 = *(const float*)(sm + O_OB + 4);
            float s2 = *(const float*)(sm + O_OB + 8);
            const float* row = (const float*)(sm + O_STG) + (u32)p * 129;
            for (int m = 0; m < HH; ++m) {
                float v = row[m];
                s0 = fmaf(v, *(const float*)(sm + O_OW + m * 4), s0);
                s1 = fmaf(v, *(const float*)(sm + O_OW + (HH + m) * 4), s1);
                s2 = fmaf(v, *(const float*)(sm + O_OW + (2 * HH + m) * 4), s2);
            }
            float* o = dout + ((size_t)b * NN + p0 + p) * 3;
            o[0] = mk * s0; o[1] = mk * s1; o[2] = mk * s2;
        }
    }
}

// ---------------------------------------------------------------------------
extern "C" void kernel_launch(void* const* d_in, const int* in_sizes, int n_in,
                              void* d_out, int out_size)
{
    const float* x_local = (const float*)d_in[0];
    const float* context = (const float*)d_in[1];
    const float* mask    = (const float*)d_in[2];
    const float* proj_lw = (const float*)d_in[3];
    const float* proj_lb = (const float*)d_in[4];
    const float* pg0w    = (const float*)d_in[5];
    const float* pg0b    = (const float*)d_in[6];
    const float* pg1w    = (const float*)d_in[7];
    const float* pg1b    = (const float*)d_in[8];
    const float* pg2w    = (const float*)d_in[9];
    const float* pg2b    = (const float*)d_in[10];
    const float* g1w     = (const float*)d_in[11];
    const float* g1b     = (const float*)d_in[12];
    const float* g2w     = (const float*)d_in[13];
    const float* g2b     = (const float*)d_in[14];
    const float* l1w     = (const float*)d_in[15];
    const float* l1b     = (const float*)d_in[16];
    const float* l2w     = (const float*)d_in[17];
    const float* l2b     = (const float*)d_in[18];
    const float* outw    = (const float*)d_in[19];
    const float* outb    = (const float*)d_in[20];
    float* out = (float*)d_out;

    cudaFuncSetAttribute(k_local, cudaFuncAttributeMaxDynamicSharedMemorySize, SMEM_SZ);

    k_prep<<<dim3(NBLK, 2), 128>>>(l1w, l2w);
    k_proj<<<dim3(16, NT0), 256>>>(x_local, mask, proj_lw, proj_lb);
    for (int blk = 0; blk < NBLK; ++blk) {
        k_global<<<16, 1024>>>(blk == 0 ? 0 : 1, blk, context,
                               pg0w, pg0b, pg1w, pg1b, pg2w, pg2b,
                               g1w, g1b, g2w, g2b, l1w);
        k_local<<<dim3(NT, 16), 512, SMEM_SZ>>>(
            blk, blk == NBLK - 1 ? 1 : 0,
            l1b, l2b, mask, outw, outb, out);
    }
}